// round 12
// baseline (speedup 1.0000x reference)
#include <cuda_runtime.h>
#include <cuda_bf16.h>
#include <cuda_fp16.h>
#include <cstdint>
#include <cstddef>

// Problem constants
#define BB   2
#define SS   2048
#define DIMM 2048
#define HH   16
#define KVHH 4
#define HDD  128
// M = B*S = 4096, QKV N = 3072, K = 2048

// ---------------------------------------------------------------------------
// Scratch (static device globals; no allocation anywhere)
// ---------------------------------------------------------------------------
__device__ float  g_qkv[(size_t)4096 * 3072];           // qkv = x @ Wqkv^T
__device__ __half g_xh [(size_t)4096 * 2048];           // x fp16
__device__ __half g_wh [(size_t)3072 * 2048];           // concat [wq;wk;wv] fp16
__device__ __half g_ao [(size_t)4096 * 2048];           // attn out fp16 (flash writes)
__device__ __half g_woh[(size_t)2048 * 2048];           // wo fp16

// flash operands, single fp16
__device__ __half g_qf [(size_t)BB * HH  * SS * HDD];   // [b][h][s][hd] roped+scaled
__device__ __half g_kf [(size_t)BB * KVHH * SS * HDD];  // [b][kvh][s][hd] roped
__device__ __half g_vtf[(size_t)BB * KVHH * HDD * SS];  // [b][kvh][hd][s] transposed

// ---------------------------------------------------------------------------
// PTX helpers (sm_80+ baseline: cp.async + mma.sync)
// ---------------------------------------------------------------------------
__device__ __forceinline__ uint32_t s2u(const void* p) {
    uint32_t a;
    asm("{ .reg .u64 t; cvta.to.shared.u64 t, %1; cvt.u32.u64 %0, t; }" : "=r"(a) : "l"(p));
    return a;
}

#define CP_ASYNC16(dst, src) \
    asm volatile("cp.async.cg.shared.global [%0], [%1], 16;" :: "r"(dst), "l"(src) : "memory")
#define CP_COMMIT() asm volatile("cp.async.commit_group;" ::: "memory")
#define CP_WAIT(n)  asm volatile("cp.async.wait_group %0;" :: "n"(n) : "memory")

// D += A * B  (m16n8k16, row.col, fp16 in, fp32 acc)
#define MMA_F16(acc, a, b) \
    asm volatile("mma.sync.aligned.m16n8k16.row.col.f32.f16.f16.f32 " \
                 "{%0,%1,%2,%3}, {%4,%5,%6,%7}, {%8,%9}, {%0,%1,%2,%3};" \
                 : "+f"((acc)[0]), "+f"((acc)[1]), "+f"((acc)[2]), "+f"((acc)[3]) \
                 : "r"((a)[0]), "r"((a)[1]), "r"((a)[2]), "r"((a)[3]), \
                   "r"((b)[0]), "r"((b)[1]))

__device__ __forceinline__ uint32_t pack_h(float a, float b) {
    __half2 h = __floats2half2_rn(a, b);
    return *reinterpret_cast<uint32_t*>(&h);
}

// ---------------------------------------------------------------------------
// fp32 -> fp16 convert (float4 per thread)
// ---------------------------------------------------------------------------
__global__ void cvt_h_kernel(const float* __restrict__ src, __half* __restrict__ dst, long n4)
{
    long i = (long)blockIdx.x * blockDim.x + threadIdx.x;
    if (i >= n4) return;
    float4 v = reinterpret_cast<const float4*>(src)[i];
    uint2 o;
    o.x = pack_h(v.x, v.y);
    o.y = pack_h(v.z, v.w);
    *reinterpret_cast<uint2*>(dst + i * 4) = o;
}

// ---------------------------------------------------------------------------
// mma.sync fp16 GEMM: C[M,N] = A[M,K] * B[N,K]^T  (fp16 in, fp32 acc)
// Tile 128x128, BK=32, 3-stage cp.async pipeline, 256 threads (8 warps 4x2,
// warp tile 32x64). smem rows padded to 80 B -> conflict-free LDS.
// ---------------------------------------------------------------------------
#define GBM 128
#define GBN 128
#define GBK 32
#define TILE_BYTES  (128 * 80)
#define STAGE_BYTES (2 * TILE_BYTES)        // A | B
#define NSTAGE 3
#define GEMM_SMEM (NSTAGE * STAGE_BYTES)    // 61440 B

__global__ __launch_bounds__(256)
void tc_gemm_f16_kernel(const __half* __restrict__ A, const __half* __restrict__ B,
                        float* __restrict__ C, int N, int K)
{
    extern __shared__ __align__(16) char smem[];
    const uint32_t smem_u = s2u(smem);
    const int tid  = threadIdx.x;
    const int lane = tid & 31;
    const int wid  = tid >> 5;
    const int g  = lane >> 2;
    const int tg = lane & 3;
    const int warpM = (wid >> 1) * 32;
    const int warpN = (wid & 1) * 64;
    const int bm = blockIdx.y * GBM;
    const int bn = blockIdx.x * GBN;
    const int nchunk = K / GBK;

    float acc[2][8][4];
#pragma unroll
    for (int mf = 0; mf < 2; mf++)
#pragma unroll
        for (int nf = 0; nf < 8; nf++)
#pragma unroll
            for (int r = 0; r < 4; r++) acc[mf][nf][r] = 0.0f;

    auto load_stage = [&](int s, int c) {
        const int k0 = c * GBK;
        const uint32_t stg = smem_u + (uint32_t)s * STAGE_BYTES;
#pragma unroll
        for (int i = 0; i < 4; i++) {
            int f = tid + i * 256;            // 0..1023
            int tile = f >> 9;                // 0:A 1:B
            int fi = f & 511;
            int r = fi >> 2, q = fi & 3;
            const __half* src = (tile == 0) ? A + (size_t)(bm + r) * K + k0 + q * 8
                                            : B + (size_t)(bn + r) * K + k0 + q * 8;
            uint32_t dst = stg + (uint32_t)tile * TILE_BYTES + (uint32_t)r * 80 + q * 16;
            CP_ASYNC16(dst, src);
        }
    };

    auto compute_stage = [&](int s) {
        const char* stg = smem + (size_t)s * STAGE_BYTES;
        const char* pA = stg;
        const char* pB = stg + TILE_BYTES;
#pragma unroll
        for (int ks = 0; ks < 2; ks++) {
            const int cb = (ks * 16 + tg * 2) * 2;
            uint32_t a[2][4], b[8][2];
#pragma unroll
            for (int mf = 0; mf < 2; mf++) {
                const int r = warpM + mf * 16 + g;
                a[mf][0] = *(const uint32_t*)(pA + r * 80 + cb);
                a[mf][1] = *(const uint32_t*)(pA + (r + 8) * 80 + cb);
                a[mf][2] = *(const uint32_t*)(pA + r * 80 + cb + 16);
                a[mf][3] = *(const uint32_t*)(pA + (r + 8) * 80 + cb + 16);
            }
#pragma unroll
            for (int nf = 0; nf < 8; nf++) {
                const int r = warpN + nf * 8 + g;
                b[nf][0] = *(const uint32_t*)(pB + r * 80 + cb);
                b[nf][1] = *(const uint32_t*)(pB + r * 80 + cb + 16);
            }
#pragma unroll
            for (int mf = 0; mf < 2; mf++)
#pragma unroll
                for (int nf = 0; nf < 8; nf++)
                    MMA_F16(acc[mf][nf], a[mf], b[nf]);
        }
    };

    load_stage(0, 0); CP_COMMIT();
    load_stage(1, 1); CP_COMMIT();

    for (int c = 0; c < nchunk; ++c) {
        if (c + 2 < nchunk) { CP_WAIT(1); } else { CP_WAIT(0); }
        __syncthreads();
        if (c + 2 < nchunk) {
            load_stage((c + 2) % NSTAGE, c + 2);
            CP_COMMIT();
        }
        compute_stage(c % NSTAGE);
        __syncthreads();
    }

#pragma unroll
    for (int mf = 0; mf < 2; mf++) {
        const int row0 = bm + warpM + mf * 16 + g;
#pragma unroll
        for (int nf = 0; nf < 8; nf++) {
            const int col = bn + warpN + nf * 8 + tg * 2;
            float2 v0 = make_float2(acc[mf][nf][0], acc[mf][nf][1]);
            float2 v1 = make_float2(acc[mf][nf][2], acc[mf][nf][3]);
            *reinterpret_cast<float2*>(&C[(size_t)row0 * N + col]) = v0;
            *reinterpret_cast<float2*>(&C[(size_t)(row0 + 8) * N + col]) = v1;
        }
    }
}

// ---------------------------------------------------------------------------
// RoPE + scatter -> fp16 Q and K (V handled by vt_kernel)
// Covers qkv cols [0, 2560): 4096 rows x 1280 pairs.
// ---------------------------------------------------------------------------
__global__ void rope_f16_kernel(const float* __restrict__ qkv,
                                const float* __restrict__ fc,
                                __half* __restrict__ qf, __half* __restrict__ kf)
{
    const float QSCALE = 0.08838834764831845f;  // 1/sqrt(128)
    size_t idx = (size_t)blockIdx.x * blockDim.x + threadIdx.x;
    if (idx >= (size_t)4096 * 1280) return;
    int m = (int)(idx / 1280);
    int p = (int)(idx - (size_t)m * 1280);
    int n = p * 2;
    int b = m >> 11;
    int s = m & 2047;

    float2 x2 = *reinterpret_cast<const float2*>(&qkv[(size_t)m * 3072 + n]);

    __half* dst; size_t addr; float sc; int d;
    if (n < 2048) {
        int h = n >> 7; d = n & 127; sc = QSCALE;
        addr = ((size_t)(b * HH + h) * SS + s) * HDD + d;
        dst = qf;
    } else {
        int nn = n - 2048;
        int h = nn >> 7; d = nn & 127; sc = 1.0f;
        addr = ((size_t)(b * KVHH + h) * SS + s) * HDD + d;
        dst = kf;
    }
    float2 cs = *reinterpret_cast<const float2*>(&fc[(size_t)s * 128 + d]);
    float ox = (x2.x * cs.x - x2.y * cs.y) * sc;
    float oy = (x2.x * cs.y + x2.y * cs.x) * sc;
    *reinterpret_cast<uint32_t*>(dst + addr) = pack_h(ox, oy);
}

// ---------------------------------------------------------------------------
// V transpose: g_qkv V section [b,s][kvh,d] -> Vt fp16 [b,kvh][d][s]
// ---------------------------------------------------------------------------
__global__ void vt_kernel(const float* __restrict__ qkv, __half* __restrict__ vtf)
{
    __shared__ float t[32][33];
    const int s0 = blockIdx.x * 32, d0 = blockIdx.y * 32;
    const int bk = blockIdx.z;            // b*4 + kvh
    const int b = bk >> 2, kvh = bk & 3;
    const int tx = threadIdx.x, ty = threadIdx.y;
#pragma unroll
    for (int j = 0; j < 4; j++) {
        int s = s0 + ty + j * 8;
        t[ty + j * 8][tx] = qkv[((size_t)(b * 2048 + s)) * 3072 + 2560 + kvh * 128 + d0 + tx];
    }
    __syncthreads();
#pragma unroll
    for (int j = 0; j < 4; j++) {
        int d = d0 + ty + j * 8;
        size_t o = ((size_t)bk * 128 + d) * 2048 + s0 + tx;
        vtf[o] = __float2half(t[tx][ty + j * 8]);
    }
}

// ---------------------------------------------------------------------------
// Tensor-core flash attention, single fp16 terms, fp32 accum.
// Grid (32 qblocks reversed, 32 bh), 128 threads (4 warps, m16 rows each).
// BM=BN=64.  K rows padded to 272B; Vt rows padded to 144B (conflict-free LDS).
// K and V both double-buffered: load(t+1) overlaps ALL compute of t.
// ---------------------------------------------------------------------------
#define FK(s)   ((s) * 17408)               // K bufs: 64 rows x 272B
#define FV(s)   (34816 + (s) * 18432)       // V bufs: 128 rows x 144B
#define FT_SMEM 71680

__global__ __launch_bounds__(128)
void flash_tc_kernel(const __half* __restrict__ qf_g, const __half* __restrict__ kf_g,
                     const __half* __restrict__ vtf_g, __half* __restrict__ ao)
{
    extern __shared__ __align__(16) char smem[];
    const uint32_t sb = s2u(smem);
    const int tid = threadIdx.x, lane = tid & 31, wm = tid >> 5;
    const int g = lane >> 2, tg = lane & 3;
    const int qb = 31 - (int)blockIdx.x;
    const int bh = blockIdx.y;
    const int b = bh >> 4, h = bh & 15, kvh = h >> 2;

    // ---- Q fragments (register-resident, fp16) ----------------------------
    const __half* qbp = qf_g + ((size_t)(b * HH + h) * SS + qb * 64 + wm * 16) * HDD;
    uint32_t qf[8][4];
#pragma unroll
    for (int kf = 0; kf < 8; kf++) {
        size_t o0 = (size_t)g * 128 + kf * 16 + tg * 2;
        qf[kf][0] = *(const uint32_t*)(qbp + o0);
        qf[kf][1] = *(const uint32_t*)(qbp + o0 + 8 * 128);
        qf[kf][2] = *(const uint32_t*)(qbp + o0 + 8);
        qf[kf][3] = *(const uint32_t*)(qbp + o0 + 8 * 128 + 8);
    }

    const size_t kvbase = (size_t)(b * KVHH + kvh) * SS * HDD;
    const size_t vtbase = (size_t)(b * KVHH + kvh) * HDD * SS;

    // K tile: 64 rows x 256B (=1024 x 16B); V tile: 128 rows x 128B (=1024 x 16B)
    auto load_KV = [&](int kt, int s) {
        const char* ksrc = (const char*)(kf_g + kvbase + (size_t)kt * 64 * 128);
#pragma unroll
        for (int i = 0; i < 8; i++) {
            int c = tid + i * 128;
            int key = c >> 4, q = c & 15;
            CP_ASYNC16(sb + FK(s) + key * 272 + q * 16, ksrc + key * 256 + q * 16);
        }
        const __half* vsrc = vtf_g + vtbase + (size_t)kt * 64;
#pragma unroll
        for (int i = 0; i < 8; i++) {
            int c = tid + i * 128;
            int d = c >> 3, q = c & 7;
            CP_ASYNC16(sb + FV(s) + d * 144 + q * 16, vsrc + (size_t)d * 2048 + q * 8);
        }
    };

    float of[16][4];
#pragma unroll
    for (int i = 0; i < 16; i++)
#pragma unroll
        for (int r = 0; r < 4; r++) of[i][r] = 0.0f;
    float m0 = -1e30f, m1 = -1e30f, l0 = 0.0f, l1 = 0.0f;

    const int nt = qb + 1;
    load_KV(0, 0); CP_COMMIT();

    for (int kt = 0; kt < nt; kt++) {
        const int cbuf = kt & 1;
        CP_WAIT(0);
        __syncthreads();
        if (kt + 1 < nt) { load_KV(kt + 1, cbuf ^ 1); CP_COMMIT(); }

        // ---- S = Q K^T ----------------------------------------------------
        float sacc[8][4];
#pragma unroll
        for (int nf = 0; nf < 8; nf++)
#pragma unroll
            for (int r = 0; r < 4; r++) sacc[nf][r] = 0.0f;

#pragma unroll
        for (int kf = 0; kf < 8; kf++) {
#pragma unroll
            for (int nf = 0; nf < 8; nf++) {
                const int ko = FK(cbuf) + (nf * 8 + g) * 272 + kf * 32 + tg * 4;
                uint32_t bf[2];
                bf[0] = *(const uint32_t*)(smem + ko);
                bf[1] = *(const uint32_t*)(smem + ko + 16);
                MMA_F16(sacc[nf], qf[kf], bf);
            }
        }

        // ---- causal mask on diagonal tile ---------------------------------
        if (kt == qb) {
            const int r0 = wm * 16 + g, r1 = r0 + 8;
#pragma unroll
            for (int nf = 0; nf < 8; nf++) {
                const int c0 = nf * 8 + tg * 2;
                if (c0     > r0) sacc[nf][0] = -1e30f;
                if (c0 + 1 > r0) sacc[nf][1] = -1e30f;
                if (c0     > r1) sacc[nf][2] = -1e30f;
                if (c0 + 1 > r1) sacc[nf][3] = -1e30f;
            }
        }

        // ---- online softmax; fp16 P fragments in registers ----------------
        float mx0 = -1e30f, mx1 = -1e30f;
#pragma unroll
        for (int nf = 0; nf < 8; nf++) {
            mx0 = fmaxf(mx0, fmaxf(sacc[nf][0], sacc[nf][1]));
            mx1 = fmaxf(mx1, fmaxf(sacc[nf][2], sacc[nf][3]));
        }
        mx0 = fmaxf(mx0, __shfl_xor_sync(0xffffffffu, mx0, 1));
        mx0 = fmaxf(mx0, __shfl_xor_sync(0xffffffffu, mx0, 2));
        mx1 = fmaxf(mx1, __shfl_xor_sync(0xffffffffu, mx1, 1));
        mx1 = fmaxf(mx1, __shfl_xor_sync(0xffffffffu, mx1, 2));
        const float mn0 = fmaxf(m0, mx0), mn1 = fmaxf(m1, mx1);
        const float al0 = __expf(m0 - mn0), al1 = __expf(m1 - mn1);

        uint32_t pa[4][4];
        float rs0 = 0.0f, rs1 = 0.0f;
#pragma unroll
        for (int nf = 0; nf < 8; nf++) {
            float p0 = __expf(sacc[nf][0] - mn0);
            float p1 = __expf(sacc[nf][1] - mn0);
            float p2 = __expf(sacc[nf][2] - mn1);
            float p3 = __expf(sacc[nf][3] - mn1);
            rs0 += p0 + p1;
            rs1 += p2 + p3;
            const int kfp = nf >> 1, o = (nf & 1) * 2;
            pa[kfp][o]     = pack_h(p0, p1);
            pa[kfp][o + 1] = pack_h(p2, p3);
        }
        rs0 += __shfl_xor_sync(0xffffffffu, rs0, 1);
        rs0 += __shfl_xor_sync(0xffffffffu, rs0, 2);
        rs1 += __shfl_xor_sync(0xffffffffu, rs1, 1);
        rs1 += __shfl_xor_sync(0xffffffffu, rs1, 2);
        l0 = l0 * al0 + rs0;
        l1 = l1 * al1 + rs1;
        m0 = mn0; m1 = mn1;
#pragma unroll
        for (int nfo = 0; nfo < 16; nfo++) {
            of[nfo][0] *= al0; of[nfo][1] *= al0;
            of[nfo][2] *= al1; of[nfo][3] *= al1;
        }

        // ---- O += P V -----------------------------------------------------
#pragma unroll
        for (int kfp = 0; kfp < 4; kfp++) {
#pragma unroll
            for (int nfo = 0; nfo < 16; nfo++) {
                const int vo = FV(cbuf) + (nfo * 8 + g) * 144 + kfp * 32 + tg * 4;
                uint32_t vv[2];
                vv[0] = *(const uint32_t*)(smem + vo);
                vv[1] = *(const uint32_t*)(smem + vo + 16);
                MMA_F16(of[nfo], pa[kfp], vv);
            }
        }
    }

    // ---- epilogue: normalize, write fp16 attn out [b*S+row][h*128+col] ----
    const float inv0 = 1.0f / l0, inv1 = 1.0f / l1;
    const int row0 = b * SS + qb * 64 + wm * 16 + g;
    const size_t base0 = (size_t)row0 * (HH * HDD) + (size_t)h * HDD;
    const size_t base1 = base0 + (size_t)8 * (HH * HDD);
#pragma unroll
    for (int nfo = 0; nfo < 16; nfo++) {
        const int col = nfo * 8 + tg * 2;
        *reinterpret_cast<uint32_t*>(ao + base0 + col) =
            pack_h(of[nfo][0] * inv0, of[nfo][1] * inv0);
        *reinterpret_cast<uint32_t*>(ao + base1 + col) =
            pack_h(of[nfo][2] * inv1, of[nfo][3] * inv1);
    }
}

// ---------------------------------------------------------------------------
// Host launcher
// ---------------------------------------------------------------------------
extern "C" void kernel_launch(void* const* d_in, const int* in_sizes, int n_in,
                              void* d_out, int out_size)
{
    (void)in_sizes; (void)n_in; (void)out_size;
    const float* x  = (const float*)d_in[0];
    const float* fc = (const float*)d_in[1];
    const float* wq = (const float*)d_in[2];
    const float* wk = (const float*)d_in[3];
    const float* wv = (const float*)d_in[4];
    const float* wo = (const float*)d_in[5];
    float* out = (float*)d_out;

    float* pqkv;
    __half *pxh, *pwh, *pao, *pwoh, *pqf, *pkf, *pvtf;
    cudaGetSymbolAddress((void**)&pqkv, g_qkv);
    cudaGetSymbolAddress((void**)&pxh,  g_xh);
    cudaGetSymbolAddress((void**)&pwh,  g_wh);
    cudaGetSymbolAddress((void**)&pao,  g_ao);
    cudaGetSymbolAddress((void**)&pwoh, g_woh);
    cudaGetSymbolAddress((void**)&pqf,  g_qf);
    cudaGetSymbolAddress((void**)&pkf,  g_kf);
    cudaGetSymbolAddress((void**)&pvtf, g_vtf);

    cudaFuncSetAttribute(tc_gemm_f16_kernel, cudaFuncAttributeMaxDynamicSharedMemorySize,
                         GEMM_SMEM);
    cudaFuncSetAttribute(flash_tc_kernel, cudaFuncAttributeMaxDynamicSharedMemorySize, FT_SMEM);

    // fp32 -> fp16 converts
    {
        long n4 = (long)4096 * 2048 / 4;
        cvt_h_kernel<<<(unsigned)((n4 + 255) / 256), 256>>>(x, pxh, n4);
    }
    {
        long n4 = (long)2048 * 2048 / 4;
        cvt_h_kernel<<<(unsigned)((n4 + 255) / 256), 256>>>(wq, pwh, n4);
    }
    {
        long n4 = (long)512 * 2048 / 4;
        cvt_h_kernel<<<(unsigned)((n4 + 255) / 256), 256>>>(wk, pwh + (size_t)2048 * 2048, n4);
        cvt_h_kernel<<<(unsigned)((n4 + 255) / 256), 256>>>(wv, pwh + (size_t)2560 * 2048, n4);
    }

    // QKV projection (fp16): [4096,2048] x [3072,2048]^T
    tc_gemm_f16_kernel<<<dim3(3072 / GBN, 4096 / GBM), 256, GEMM_SMEM>>>(
        pxh, pwh, pqkv, 3072, 2048);

    // RoPE -> Q/K fp16; V transpose -> Vt fp16
    rope_f16_kernel<<<20480, 256>>>(pqkv, fc, pqf, pkf);
    vt_kernel<<<dim3(64, 4, 8), dim3(32, 8)>>>(pqkv, pvtf);

    // Tensor-core flash attention (fp16) -> attn out fp16
    flash_tc_kernel<<<dim3(32, 32), 128, FT_SMEM>>>(pqf, pkf, pvtf, pao);

    // wo projection (fp16): [4096,2048] x [2048,2048]^T -> out
    {
        long n4 = (long)2048 * 2048 / 4;
        cvt_h_kernel<<<(unsigned)((n4 + 255) / 256), 256>>>(wo, pwoh, n4);
    }
    tc_gemm_f16_kernel<<<dim3(2048 / GBN, 4096 / GBM), 256, GEMM_SMEM>>>(
        pao, pwoh, out, 2048, 2048);
}

// round 13
// speedup vs baseline: 1.0252x; 1.0252x over previous
#include <cuda_runtime.h>
#include <cuda_bf16.h>
#include <cuda_fp16.h>
#include <cstdint>
#include <cstddef>

// Problem constants
#define BB   2
#define SS   2048
#define DIMM 2048
#define HH   16
#define KVHH 4
#define HDD  128
// M = B*S = 4096, QKV N = 3072, K = 2048

// ---------------------------------------------------------------------------
// Scratch (static device globals; no allocation anywhere)
// ---------------------------------------------------------------------------
__device__ float  g_qkv[(size_t)4096 * 3072];           // qkv = x @ Wqkv^T
__device__ __half g_xh [(size_t)4096 * 2048];           // x fp16
__device__ __half g_wh [(size_t)3072 * 2048];           // concat [wq;wk;wv] fp16
__device__ __half g_ao [(size_t)4096 * 2048];           // attn out fp16 (flash writes)
__device__ __half g_woh[(size_t)2048 * 2048];           // wo fp16

// flash operands, single fp16
__device__ __half g_qf [(size_t)BB * HH  * SS * HDD];   // [b][h][s][hd] roped+scaled
__device__ __half g_kf [(size_t)BB * KVHH * SS * HDD];  // [b][kvh][s][hd] roped
__device__ __half g_vtf[(size_t)BB * KVHH * HDD * SS];  // [b][kvh][hd][s] transposed

// ---------------------------------------------------------------------------
// PTX helpers (sm_80+ baseline: cp.async + mma.sync)
// ---------------------------------------------------------------------------
__device__ __forceinline__ uint32_t s2u(const void* p) {
    uint32_t a;
    asm("{ .reg .u64 t; cvta.to.shared.u64 t, %1; cvt.u32.u64 %0, t; }" : "=r"(a) : "l"(p));
    return a;
}

#define CP_ASYNC16(dst, src) \
    asm volatile("cp.async.cg.shared.global [%0], [%1], 16;" :: "r"(dst), "l"(src) : "memory")
#define CP_COMMIT() asm volatile("cp.async.commit_group;" ::: "memory")
#define CP_WAIT(n)  asm volatile("cp.async.wait_group %0;" :: "n"(n) : "memory")

// D += A * B  (m16n8k16, row.col, fp16 in, fp32 acc)
#define MMA_F16(acc, a, b) \
    asm volatile("mma.sync.aligned.m16n8k16.row.col.f32.f16.f16.f32 " \
                 "{%0,%1,%2,%3}, {%4,%5,%6,%7}, {%8,%9}, {%0,%1,%2,%3};" \
                 : "+f"((acc)[0]), "+f"((acc)[1]), "+f"((acc)[2]), "+f"((acc)[3]) \
                 : "r"((a)[0]), "r"((a)[1]), "r"((a)[2]), "r"((a)[3]), \
                   "r"((b)[0]), "r"((b)[1]))

__device__ __forceinline__ uint32_t pack_h(float a, float b) {
    __half2 h = __floats2half2_rn(a, b);
    return *reinterpret_cast<uint32_t*>(&h);
}

// ---------------------------------------------------------------------------
// fp32 -> fp16 convert (float4 per thread)
// ---------------------------------------------------------------------------
__global__ void cvt_h_kernel(const float* __restrict__ src, __half* __restrict__ dst, long n4)
{
    long i = (long)blockIdx.x * blockDim.x + threadIdx.x;
    if (i >= n4) return;
    float4 v = reinterpret_cast<const float4*>(src)[i];
    uint2 o;
    o.x = pack_h(v.x, v.y);
    o.y = pack_h(v.z, v.w);
    *reinterpret_cast<uint2*>(dst + i * 4) = o;
}

// ---------------------------------------------------------------------------
// mma.sync fp16 GEMM: C[M,N] = A[M,K] * B[N,K]^T  (fp16 in, fp32 acc)
// Tile 128x128, BK=32, 3-stage cp.async pipeline, 256 threads (8 warps 4x2,
// warp tile 32x64). smem rows padded to 80 B -> conflict-free LDS.
// ---------------------------------------------------------------------------
#define GBM 128
#define GBN 128
#define GBK 32
#define TILE_BYTES  (128 * 80)
#define STAGE_BYTES (2 * TILE_BYTES)        // A | B
#define NSTAGE 3
#define GEMM_SMEM (NSTAGE * STAGE_BYTES)    // 61440 B

__global__ __launch_bounds__(256)
void tc_gemm_f16_kernel(const __half* __restrict__ A, const __half* __restrict__ B,
                        float* __restrict__ C, int N, int K)
{
    extern __shared__ __align__(16) char smem[];
    const uint32_t smem_u = s2u(smem);
    const int tid  = threadIdx.x;
    const int lane = tid & 31;
    const int wid  = tid >> 5;
    const int g  = lane >> 2;
    const int tg = lane & 3;
    const int warpM = (wid >> 1) * 32;
    const int warpN = (wid & 1) * 64;
    const int bm = blockIdx.y * GBM;
    const int bn = blockIdx.x * GBN;
    const int nchunk = K / GBK;

    float acc[2][8][4];
#pragma unroll
    for (int mf = 0; mf < 2; mf++)
#pragma unroll
        for (int nf = 0; nf < 8; nf++)
#pragma unroll
            for (int r = 0; r < 4; r++) acc[mf][nf][r] = 0.0f;

    auto load_stage = [&](int s, int c) {
        const int k0 = c * GBK;
        const uint32_t stg = smem_u + (uint32_t)s * STAGE_BYTES;
#pragma unroll
        for (int i = 0; i < 4; i++) {
            int f = tid + i * 256;            // 0..1023
            int tile = f >> 9;                // 0:A 1:B
            int fi = f & 511;
            int r = fi >> 2, q = fi & 3;
            const __half* src = (tile == 0) ? A + (size_t)(bm + r) * K + k0 + q * 8
                                            : B + (size_t)(bn + r) * K + k0 + q * 8;
            uint32_t dst = stg + (uint32_t)tile * TILE_BYTES + (uint32_t)r * 80 + q * 16;
            CP_ASYNC16(dst, src);
        }
    };

    auto compute_stage = [&](int s) {
        const char* stg = smem + (size_t)s * STAGE_BYTES;
        const char* pA = stg;
        const char* pB = stg + TILE_BYTES;
#pragma unroll
        for (int ks = 0; ks < 2; ks++) {
            const int cb = (ks * 16 + tg * 2) * 2;
            uint32_t a[2][4], b[8][2];
#pragma unroll
            for (int mf = 0; mf < 2; mf++) {
                const int r = warpM + mf * 16 + g;
                a[mf][0] = *(const uint32_t*)(pA + r * 80 + cb);
                a[mf][1] = *(const uint32_t*)(pA + (r + 8) * 80 + cb);
                a[mf][2] = *(const uint32_t*)(pA + r * 80 + cb + 16);
                a[mf][3] = *(const uint32_t*)(pA + (r + 8) * 80 + cb + 16);
            }
#pragma unroll
            for (int nf = 0; nf < 8; nf++) {
                const int r = warpN + nf * 8 + g;
                b[nf][0] = *(const uint32_t*)(pB + r * 80 + cb);
                b[nf][1] = *(const uint32_t*)(pB + r * 80 + cb + 16);
            }
#pragma unroll
            for (int mf = 0; mf < 2; mf++)
#pragma unroll
                for (int nf = 0; nf < 8; nf++)
                    MMA_F16(acc[mf][nf], a[mf], b[nf]);
        }
    };

    load_stage(0, 0); CP_COMMIT();
    load_stage(1, 1); CP_COMMIT();

    for (int c = 0; c < nchunk; ++c) {
        if (c + 2 < nchunk) { CP_WAIT(1); } else { CP_WAIT(0); }
        __syncthreads();
        if (c + 2 < nchunk) {
            load_stage((c + 2) % NSTAGE, c + 2);
            CP_COMMIT();
        }
        compute_stage(c % NSTAGE);
        __syncthreads();
    }

#pragma unroll
    for (int mf = 0; mf < 2; mf++) {
        const int row0 = bm + warpM + mf * 16 + g;
#pragma unroll
        for (int nf = 0; nf < 8; nf++) {
            const int col = bn + warpN + nf * 8 + tg * 2;
            float2 v0 = make_float2(acc[mf][nf][0], acc[mf][nf][1]);
            float2 v1 = make_float2(acc[mf][nf][2], acc[mf][nf][3]);
            *reinterpret_cast<float2*>(&C[(size_t)row0 * N + col]) = v0;
            *reinterpret_cast<float2*>(&C[(size_t)(row0 + 8) * N + col]) = v1;
        }
    }
}

// ---------------------------------------------------------------------------
// RoPE + scatter -> fp16 Q and K (V handled by vt_kernel)
// ---------------------------------------------------------------------------
__global__ void rope_f16_kernel(const float* __restrict__ qkv,
                                const float* __restrict__ fc,
                                __half* __restrict__ qf, __half* __restrict__ kf)
{
    const float QSCALE = 0.08838834764831845f;  // 1/sqrt(128)
    size_t idx = (size_t)blockIdx.x * blockDim.x + threadIdx.x;
    if (idx >= (size_t)4096 * 1280) return;
    int m = (int)(idx / 1280);
    int p = (int)(idx - (size_t)m * 1280);
    int n = p * 2;
    int b = m >> 11;
    int s = m & 2047;

    float2 x2 = *reinterpret_cast<const float2*>(&qkv[(size_t)m * 3072 + n]);

    __half* dst; size_t addr; float sc; int d;
    if (n < 2048) {
        int h = n >> 7; d = n & 127; sc = QSCALE;
        addr = ((size_t)(b * HH + h) * SS + s) * HDD + d;
        dst = qf;
    } else {
        int nn = n - 2048;
        int h = nn >> 7; d = nn & 127; sc = 1.0f;
        addr = ((size_t)(b * KVHH + h) * SS + s) * HDD + d;
        dst = kf;
    }
    float2 cs = *reinterpret_cast<const float2*>(&fc[(size_t)s * 128 + d]);
    float ox = (x2.x * cs.x - x2.y * cs.y) * sc;
    float oy = (x2.x * cs.y + x2.y * cs.x) * sc;
    *reinterpret_cast<uint32_t*>(dst + addr) = pack_h(ox, oy);
}

// ---------------------------------------------------------------------------
// V transpose: g_qkv V section [b,s][kvh,d] -> Vt fp16 [b,kvh][d][s]
// ---------------------------------------------------------------------------
__global__ void vt_kernel(const float* __restrict__ qkv, __half* __restrict__ vtf)
{
    __shared__ float t[32][33];
    const int s0 = blockIdx.x * 32, d0 = blockIdx.y * 32;
    const int bk = blockIdx.z;            // b*4 + kvh
    const int b = bk >> 2, kvh = bk & 3;
    const int tx = threadIdx.x, ty = threadIdx.y;
#pragma unroll
    for (int j = 0; j < 4; j++) {
        int s = s0 + ty + j * 8;
        t[ty + j * 8][tx] = qkv[((size_t)(b * 2048 + s)) * 3072 + 2560 + kvh * 128 + d0 + tx];
    }
    __syncthreads();
#pragma unroll
    for (int j = 0; j < 4; j++) {
        int d = d0 + ty + j * 8;
        size_t o = ((size_t)bk * 128 + d) * 2048 + s0 + tx;
        vtf[o] = __float2half(t[tx][ty + j * 8]);
    }
}

// ---------------------------------------------------------------------------
// Tensor-core flash attention, fp16, BM=128 (2 q-subtiles), BN=64.
// Grid (16 qblocks reversed, 32 bh), 256 threads = 8 warps, each owning m16
// q-rows. K rows 272B-padded, Vt rows 144B-padded (conflict-free LDS).
// K+V double-buffered; load(t+1) overlaps all compute of t.  Per 32KB KV tile
// the CTA now does 1024 HMMA (2x R12) and K/V L2 traffic is halved.
// ---------------------------------------------------------------------------
#define FK(s)   ((s) * 17408)               // K bufs: 64 rows x 272B
#define FV(s)   (34816 + (s) * 18432)       // V bufs: 128 rows x 144B
#define FT_SMEM 71680

__global__ __launch_bounds__(256)
void flash_tc_kernel(const __half* __restrict__ qf_g, const __half* __restrict__ kf_g,
                     const __half* __restrict__ vtf_g, __half* __restrict__ ao)
{
    extern __shared__ __align__(16) char smem[];
    const uint32_t sb = s2u(smem);
    const int tid = threadIdx.x, lane = tid & 31, wm = tid >> 5;   // wm 0..7
    const int g = lane >> 2, tg = lane & 3;
    const int qb = (int)gridDim.x - 1 - (int)blockIdx.x;           // 15..0, long first
    const int bh = blockIdx.y;
    const int b = bh >> 4, h = bh & 15, kvh = h >> 2;

    // ---- Q fragments (register-resident, fp16); rows qb*128 + wm*16 + {g, g+8}
    const __half* qbp = qf_g + ((size_t)(b * HH + h) * SS + qb * 128 + wm * 16) * HDD;
    uint32_t qf[8][4];
#pragma unroll
    for (int kf = 0; kf < 8; kf++) {
        size_t o0 = (size_t)g * 128 + kf * 16 + tg * 2;
        qf[kf][0] = *(const uint32_t*)(qbp + o0);
        qf[kf][1] = *(const uint32_t*)(qbp + o0 + 8 * 128);
        qf[kf][2] = *(const uint32_t*)(qbp + o0 + 8);
        qf[kf][3] = *(const uint32_t*)(qbp + o0 + 8 * 128 + 8);
    }

    const size_t kvbase = (size_t)(b * KVHH + kvh) * SS * HDD;
    const size_t vtbase = (size_t)(b * KVHH + kvh) * HDD * SS;

    // K tile: 64 rows x 256B (=1024 x 16B); V tile: 128 rows x 128B (=1024 x 16B)
    auto load_KV = [&](int kt, int s) {
        const char* ksrc = (const char*)(kf_g + kvbase + (size_t)kt * 64 * 128);
#pragma unroll
        for (int i = 0; i < 4; i++) {
            int c = tid + i * 256;
            int key = c >> 4, q = c & 15;
            CP_ASYNC16(sb + FK(s) + key * 272 + q * 16, ksrc + key * 256 + q * 16);
        }
        const __half* vsrc = vtf_g + vtbase + (size_t)kt * 64;
#pragma unroll
        for (int i = 0; i < 4; i++) {
            int c = tid + i * 256;
            int d = c >> 3, q = c & 7;
            CP_ASYNC16(sb + FV(s) + d * 144 + q * 16, vsrc + (size_t)d * 2048 + q * 8);
        }
    };

    float of[16][4];
#pragma unroll
    for (int i = 0; i < 16; i++)
#pragma unroll
        for (int r = 0; r < 4; r++) of[i][r] = 0.0f;
    float m0 = -1e30f, m1 = -1e30f, l0 = 0.0f, l1 = 0.0f;

    const int nt = 2 * qb + 2;
    const int qrow0 = qb * 128 + wm * 16 + g;      // global q row (acc rows 0,1)
    const int qrow1 = qrow0 + 8;                   // global q row (acc rows 2,3)

    load_KV(0, 0); CP_COMMIT();

    for (int kt = 0; kt < nt; kt++) {
        const int cbuf = kt & 1;
        CP_WAIT(0);
        __syncthreads();
        if (kt + 1 < nt) { load_KV(kt + 1, cbuf ^ 1); CP_COMMIT(); }

        // ---- S = Q K^T ----------------------------------------------------
        float sacc[8][4];
#pragma unroll
        for (int nf = 0; nf < 8; nf++)
#pragma unroll
            for (int r = 0; r < 4; r++) sacc[nf][r] = 0.0f;

#pragma unroll
        for (int kf = 0; kf < 8; kf++) {
#pragma unroll
            for (int nf = 0; nf < 8; nf++) {
                const int ko = FK(cbuf) + (nf * 8 + g) * 272 + kf * 32 + tg * 4;
                uint32_t bf[2];
                bf[0] = *(const uint32_t*)(smem + ko);
                bf[1] = *(const uint32_t*)(smem + ko + 16);
                MMA_F16(sacc[nf], qf[kf], bf);
            }
        }

        // ---- causal mask (last two tiles of this q-block) -----------------
        if (kt >= nt - 2) {
            const int cbase = kt * 64;
#pragma unroll
            for (int nf = 0; nf < 8; nf++) {
                const int c0 = cbase + nf * 8 + tg * 2;
                if (c0     > qrow0) sacc[nf][0] = -1e30f;
                if (c0 + 1 > qrow0) sacc[nf][1] = -1e30f;
                if (c0     > qrow1) sacc[nf][2] = -1e30f;
                if (c0 + 1 > qrow1) sacc[nf][3] = -1e30f;
            }
        }

        // ---- online softmax; fp16 P fragments in registers ----------------
        float mx0 = -1e30f, mx1 = -1e30f;
#pragma unroll
        for (int nf = 0; nf < 8; nf++) {
            mx0 = fmaxf(mx0, fmaxf(sacc[nf][0], sacc[nf][1]));
            mx1 = fmaxf(mx1, fmaxf(sacc[nf][2], sacc[nf][3]));
        }
        mx0 = fmaxf(mx0, __shfl_xor_sync(0xffffffffu, mx0, 1));
        mx0 = fmaxf(mx0, __shfl_xor_sync(0xffffffffu, mx0, 2));
        mx1 = fmaxf(mx1, __shfl_xor_sync(0xffffffffu, mx1, 1));
        mx1 = fmaxf(mx1, __shfl_xor_sync(0xffffffffu, mx1, 2));
        const float mn0 = fmaxf(m0, mx0), mn1 = fmaxf(m1, mx1);
        const float al0 = __expf(m0 - mn0), al1 = __expf(m1 - mn1);

        uint32_t pa[4][4];
        float rs0 = 0.0f, rs1 = 0.0f;
#pragma unroll
        for (int nf = 0; nf < 8; nf++) {
            float p0 = __expf(sacc[nf][0] - mn0);
            float p1 = __expf(sacc[nf][1] - mn0);
            float p2 = __expf(sacc[nf][2] - mn1);
            float p3 = __expf(sacc[nf][3] - mn1);
            rs0 += p0 + p1;
            rs1 += p2 + p3;
            const int kfp = nf >> 1, o = (nf & 1) * 2;
            pa[kfp][o]     = pack_h(p0, p1);
            pa[kfp][o + 1] = pack_h(p2, p3);
        }
        rs0 += __shfl_xor_sync(0xffffffffu, rs0, 1);
        rs0 += __shfl_xor_sync(0xffffffffu, rs0, 2);
        rs1 += __shfl_xor_sync(0xffffffffu, rs1, 1);
        rs1 += __shfl_xor_sync(0xffffffffu, rs1, 2);
        l0 = l0 * al0 + rs0;
        l1 = l1 * al1 + rs1;
        m0 = mn0; m1 = mn1;
#pragma unroll
        for (int nfo = 0; nfo < 16; nfo++) {
            of[nfo][0] *= al0; of[nfo][1] *= al0;
            of[nfo][2] *= al1; of[nfo][3] *= al1;
        }

        // ---- O += P V -----------------------------------------------------
#pragma unroll
        for (int kfp = 0; kfp < 4; kfp++) {
#pragma unroll
            for (int nfo = 0; nfo < 16; nfo++) {
                const int vo = FV(cbuf) + (nfo * 8 + g) * 144 + kfp * 32 + tg * 4;
                uint32_t vv[2];
                vv[0] = *(const uint32_t*)(smem + vo);
                vv[1] = *(const uint32_t*)(smem + vo + 16);
                MMA_F16(of[nfo], pa[kfp], vv);
            }
        }
    }

    // ---- epilogue: normalize, write fp16 attn out [b*S+row][h*128+col] ----
    const float inv0 = 1.0f / l0, inv1 = 1.0f / l1;
    const int row0 = b * SS + qb * 128 + wm * 16 + g;
    const size_t base0 = (size_t)row0 * (HH * HDD) + (size_t)h * HDD;
    const size_t base1 = base0 + (size_t)8 * (HH * HDD);
#pragma unroll
    for (int nfo = 0; nfo < 16; nfo++) {
        const int col = nfo * 8 + tg * 2;
        *reinterpret_cast<uint32_t*>(ao + base0 + col) =
            pack_h(of[nfo][0] * inv0, of[nfo][1] * inv0);
        *reinterpret_cast<uint32_t*>(ao + base1 + col) =
            pack_h(of[nfo][2] * inv1, of[nfo][3] * inv1);
    }
}

// ---------------------------------------------------------------------------
// Host launcher
// ---------------------------------------------------------------------------
extern "C" void kernel_launch(void* const* d_in, const int* in_sizes, int n_in,
                              void* d_out, int out_size)
{
    (void)in_sizes; (void)n_in; (void)out_size;
    const float* x  = (const float*)d_in[0];
    const float* fc = (const float*)d_in[1];
    const float* wq = (const float*)d_in[2];
    const float* wk = (const float*)d_in[3];
    const float* wv = (const float*)d_in[4];
    const float* wo = (const float*)d_in[5];
    float* out = (float*)d_out;

    float* pqkv;
    __half *pxh, *pwh, *pao, *pwoh, *pqf, *pkf, *pvtf;
    cudaGetSymbolAddress((void**)&pqkv, g_qkv);
    cudaGetSymbolAddress((void**)&pxh,  g_xh);
    cudaGetSymbolAddress((void**)&pwh,  g_wh);
    cudaGetSymbolAddress((void**)&pao,  g_ao);
    cudaGetSymbolAddress((void**)&pwoh, g_woh);
    cudaGetSymbolAddress((void**)&pqf,  g_qf);
    cudaGetSymbolAddress((void**)&pkf,  g_kf);
    cudaGetSymbolAddress((void**)&pvtf, g_vtf);

    cudaFuncSetAttribute(tc_gemm_f16_kernel, cudaFuncAttributeMaxDynamicSharedMemorySize,
                         GEMM_SMEM);
    cudaFuncSetAttribute(flash_tc_kernel, cudaFuncAttributeMaxDynamicSharedMemorySize, FT_SMEM);

    // fp32 -> fp16 converts
    {
        long n4 = (long)4096 * 2048 / 4;
        cvt_h_kernel<<<(unsigned)((n4 + 255) / 256), 256>>>(x, pxh, n4);
    }
    {
        long n4 = (long)2048 * 2048 / 4;
        cvt_h_kernel<<<(unsigned)((n4 + 255) / 256), 256>>>(wq, pwh, n4);
    }
    {
        long n4 = (long)512 * 2048 / 4;
        cvt_h_kernel<<<(unsigned)((n4 + 255) / 256), 256>>>(wk, pwh + (size_t)2048 * 2048, n4);
        cvt_h_kernel<<<(unsigned)((n4 + 255) / 256), 256>>>(wv, pwh + (size_t)2560 * 2048, n4);
    }

    // QKV projection (fp16): [4096,2048] x [3072,2048]^T
    tc_gemm_f16_kernel<<<dim3(3072 / GBN, 4096 / GBM), 256, GEMM_SMEM>>>(
        pxh, pwh, pqkv, 3072, 2048);

    // RoPE -> Q/K fp16; V transpose -> Vt fp16
    rope_f16_kernel<<<20480, 256>>>(pqkv, fc, pqf, pkf);
    vt_kernel<<<dim3(64, 4, 8), dim3(32, 8)>>>(pqkv, pvtf);

    // Tensor-core flash attention (fp16, BM=128) -> attn out fp16
    flash_tc_kernel<<<dim3(16, 32), 256, FT_SMEM>>>(pqf, pkf, pvtf, pao);

    // wo projection (fp16): [4096,2048] x [2048,2048]^T -> out
    {
        long n4 = (long)2048 * 2048 / 4;
        cvt_h_kernel<<<(unsigned)((n4 + 255) / 256), 256>>>(wo, pwoh, n4);
    }
    tc_gemm_f16_kernel<<<dim3(2048 / GBN, 4096 / GBM), 256, GEMM_SMEM>>>(
        pao, pwoh, out, 2048, 2048);
}

// round 15
// speedup vs baseline: 1.1893x; 1.1600x over previous
#include <cuda_runtime.h>
#include <cuda_bf16.h>
#include <cuda_fp16.h>
#include <cstdint>
#include <cstddef>

// Problem constants
#define BB   2
#define SS   2048
#define DIMM 2048
#define HH   16
#define KVHH 4
#define HDD  128
// M = B*S = 4096, QKV N = 3072, K = 2048

// ---------------------------------------------------------------------------
// Scratch (static device globals; no allocation anywhere)
// ---------------------------------------------------------------------------
__device__ float  g_qkv[(size_t)4096 * 3072];           // only V cols [2560,3072) written
__device__ __half g_xh [(size_t)4096 * 2048];           // x fp16
__device__ __half g_wh [(size_t)3072 * 2048];           // concat [wq;wk;wv] fp16
__device__ __half g_ao [(size_t)4096 * 2048];           // attn out fp16 (flash writes)
__device__ __half g_woh[(size_t)2048 * 2048];           // wo fp16

// flash operands, bf16 hi/lo (split — measured-good accuracy hedge)
__device__ __nv_bfloat16 g_qh [(size_t)BB * HH  * SS * HDD];  // roped+scaled
__device__ __nv_bfloat16 g_ql [(size_t)BB * HH  * SS * HDD];
__device__ __nv_bfloat16 g_kh [(size_t)BB * KVHH * SS * HDD]; // roped
__device__ __nv_bfloat16 g_kl [(size_t)BB * KVHH * SS * HDD];
__device__ __nv_bfloat16 g_vth[(size_t)BB * KVHH * HDD * SS]; // [b][kvh][d][s]
__device__ __nv_bfloat16 g_vtl[(size_t)BB * KVHH * HDD * SS];

// ---------------------------------------------------------------------------
// PTX helpers (sm_80+ baseline: cp.async + mma.sync)
// ---------------------------------------------------------------------------
__device__ __forceinline__ uint32_t s2u(const void* p) {
    uint32_t a;
    asm("{ .reg .u64 t; cvta.to.shared.u64 t, %1; cvt.u32.u64 %0, t; }" : "=r"(a) : "l"(p));
    return a;
}

#define CP_ASYNC16(dst, src) \
    asm volatile("cp.async.cg.shared.global [%0], [%1], 16;" :: "r"(dst), "l"(src) : "memory")
#define CP_COMMIT() asm volatile("cp.async.commit_group;" ::: "memory")
#define CP_WAIT(n)  asm volatile("cp.async.wait_group %0;" :: "n"(n) : "memory")

#define MMA_BF16(acc, a, b) \
    asm volatile("mma.sync.aligned.m16n8k16.row.col.f32.bf16.bf16.f32 " \
                 "{%0,%1,%2,%3}, {%4,%5,%6,%7}, {%8,%9}, {%0,%1,%2,%3};" \
                 : "+f"((acc)[0]), "+f"((acc)[1]), "+f"((acc)[2]), "+f"((acc)[3]) \
                 : "r"((a)[0]), "r"((a)[1]), "r"((a)[2]), "r"((a)[3]), \
                   "r"((b)[0]), "r"((b)[1]))

#define MMA_F16(acc, a, b) \
    asm volatile("mma.sync.aligned.m16n8k16.row.col.f32.f16.f16.f32 " \
                 "{%0,%1,%2,%3}, {%4,%5,%6,%7}, {%8,%9}, {%0,%1,%2,%3};" \
                 : "+f"((acc)[0]), "+f"((acc)[1]), "+f"((acc)[2]), "+f"((acc)[3]) \
                 : "r"((a)[0]), "r"((a)[1]), "r"((a)[2]), "r"((a)[3]), \
                   "r"((b)[0]), "r"((b)[1]))

__device__ __forceinline__ uint32_t pack_bf16(float a, float b) {
    uint32_t lo = __bfloat16_as_ushort(__float2bfloat16(a));
    uint32_t hi = __bfloat16_as_ushort(__float2bfloat16(b));
    return lo | (hi << 16);
}
__device__ __forceinline__ uint32_t pack_h(float a, float b) {
    __half2 h = __floats2half2_rn(a, b);
    return *reinterpret_cast<uint32_t*>(&h);
}

// ---------------------------------------------------------------------------
// fp32 -> fp16 convert (float4 per thread)
// ---------------------------------------------------------------------------
__global__ void cvt_h_kernel(const float* __restrict__ src, __half* __restrict__ dst, long n4)
{
    long i = (long)blockIdx.x * blockDim.x + threadIdx.x;
    if (i >= n4) return;
    float4 v = reinterpret_cast<const float4*>(src)[i];
    uint2 o;
    o.x = pack_h(v.x, v.y);
    o.y = pack_h(v.z, v.w);
    *reinterpret_cast<uint2*>(dst + i * 4) = o;
}

// ---------------------------------------------------------------------------
// Shared GEMM guts: mma.sync fp16, tile 128x128, BK=32, 3-stage cp.async.
// ---------------------------------------------------------------------------
#define GBM 128
#define GBN 128
#define GBK 32
#define TILE_BYTES  (128 * 80)
#define STAGE_BYTES (2 * TILE_BYTES)        // A | B
#define NSTAGE 3
#define GEMM_SMEM (NSTAGE * STAGE_BYTES)    // 61440 B

// mainloop macro-ish via inline function computing acc for one CTA
struct GemmCtx {
    int tid, lane, wid, g, tg, warpM, warpN, bm, bn;
};

__device__ __forceinline__ void gemm_mainloop(
    const __half* __restrict__ A, const __half* __restrict__ B,
    int K, char* smem, const GemmCtx& cx, float acc[2][8][4])
{
    const uint32_t smem_u = s2u(smem);
    const int nchunk = K / GBK;

#pragma unroll
    for (int mf = 0; mf < 2; mf++)
#pragma unroll
        for (int nf = 0; nf < 8; nf++)
#pragma unroll
            for (int r = 0; r < 4; r++) acc[mf][nf][r] = 0.0f;

    auto load_stage = [&](int s, int c) {
        const int k0 = c * GBK;
        const uint32_t stg = smem_u + (uint32_t)s * STAGE_BYTES;
#pragma unroll
        for (int i = 0; i < 4; i++) {
            int f = cx.tid + i * 256;
            int tile = f >> 9;
            int fi = f & 511;
            int r = fi >> 2, q = fi & 3;
            const __half* src = (tile == 0) ? A + (size_t)(cx.bm + r) * K + k0 + q * 8
                                            : B + (size_t)(cx.bn + r) * K + k0 + q * 8;
            uint32_t dst = stg + (uint32_t)tile * TILE_BYTES + (uint32_t)r * 80 + q * 16;
            CP_ASYNC16(dst, src);
        }
    };

    auto compute_stage = [&](int s) {
        const char* stg = smem + (size_t)s * STAGE_BYTES;
        const char* pA = stg;
        const char* pB = stg + TILE_BYTES;
#pragma unroll
        for (int ks = 0; ks < 2; ks++) {
            const int cb = (ks * 16 + cx.tg * 2) * 2;
            uint32_t a[2][4], b[8][2];
#pragma unroll
            for (int mf = 0; mf < 2; mf++) {
                const int r = cx.warpM + mf * 16 + cx.g;
                a[mf][0] = *(const uint32_t*)(pA + r * 80 + cb);
                a[mf][1] = *(const uint32_t*)(pA + (r + 8) * 80 + cb);
                a[mf][2] = *(const uint32_t*)(pA + r * 80 + cb + 16);
                a[mf][3] = *(const uint32_t*)(pA + (r + 8) * 80 + cb + 16);
            }
#pragma unroll
            for (int nf = 0; nf < 8; nf++) {
                const int r = cx.warpN + nf * 8 + cx.g;
                b[nf][0] = *(const uint32_t*)(pB + r * 80 + cb);
                b[nf][1] = *(const uint32_t*)(pB + r * 80 + cb + 16);
            }
#pragma unroll
            for (int mf = 0; mf < 2; mf++)
#pragma unroll
                for (int nf = 0; nf < 8; nf++)
                    MMA_F16(acc[mf][nf], a[mf], b[nf]);
        }
    };

    load_stage(0, 0); CP_COMMIT();
    load_stage(1, 1); CP_COMMIT();

    for (int c = 0; c < nchunk; ++c) {
        if (c + 2 < nchunk) { CP_WAIT(1); } else { CP_WAIT(0); }
        __syncthreads();
        if (c + 2 < nchunk) {
            load_stage((c + 2) % NSTAGE, c + 2);
            CP_COMMIT();
        }
        compute_stage(c % NSTAGE);
        __syncthreads();
    }
}

// ---------------------------------------------------------------------------
// Plain fp16 GEMM -> fp32 C  (used for wo projection)
// ---------------------------------------------------------------------------
__global__ __launch_bounds__(256)
void tc_gemm_f16_kernel(const __half* __restrict__ A, const __half* __restrict__ B,
                        float* __restrict__ C, int N, int K)
{
    extern __shared__ __align__(16) char smem[];
    GemmCtx cx;
    cx.tid = threadIdx.x; cx.lane = cx.tid & 31; cx.wid = cx.tid >> 5;
    cx.g = cx.lane >> 2; cx.tg = cx.lane & 3;
    cx.warpM = (cx.wid >> 1) * 32; cx.warpN = (cx.wid & 1) * 64;
    cx.bm = blockIdx.y * GBM; cx.bn = blockIdx.x * GBN;

    float acc[2][8][4];
    gemm_mainloop(A, B, K, smem, cx, acc);

#pragma unroll
    for (int mf = 0; mf < 2; mf++) {
        const int row0 = cx.bm + cx.warpM + mf * 16 + cx.g;
#pragma unroll
        for (int nf = 0; nf < 8; nf++) {
            const int col = cx.bn + cx.warpN + nf * 8 + cx.tg * 2;
            float2 v0 = make_float2(acc[mf][nf][0], acc[mf][nf][1]);
            float2 v1 = make_float2(acc[mf][nf][2], acc[mf][nf][3]);
            *reinterpret_cast<float2*>(&C[(size_t)row0 * N + col]) = v0;
            *reinterpret_cast<float2*>(&C[(size_t)(row0 + 8) * N + col]) = v1;
        }
    }
}

// ---------------------------------------------------------------------------
// QKV GEMM with fused RoPE epilogue.
// Cols [0,2048): Q -> rope+scale -> bf16 hi/lo into g_qh/g_ql [b][h][s][d]
// Cols [2048,2560): K -> rope -> bf16 hi/lo into g_kh/g_kl [b][kvh][s][d]
// Cols [2560,3072): V -> fp32 into g_qkv (vt_kernel transposes later)
// Accumulator pairs (tg*2, tg*2+1) are exactly the rope pairs (d even).
// ---------------------------------------------------------------------------
__global__ __launch_bounds__(256)
void tc_gemm_qkv_kernel(const __half* __restrict__ A, const __half* __restrict__ B,
                        const float* __restrict__ fc,
                        float* __restrict__ Cv,
                        __nv_bfloat16* __restrict__ qh, __nv_bfloat16* __restrict__ ql,
                        __nv_bfloat16* __restrict__ kh, __nv_bfloat16* __restrict__ kl)
{
    extern __shared__ __align__(16) char smem[];
    GemmCtx cx;
    cx.tid = threadIdx.x; cx.lane = cx.tid & 31; cx.wid = cx.tid >> 5;
    cx.g = cx.lane >> 2; cx.tg = cx.lane & 3;
    cx.warpM = (cx.wid >> 1) * 32; cx.warpN = (cx.wid & 1) * 64;
    cx.bm = blockIdx.y * GBM; cx.bn = blockIdx.x * GBN;

    float acc[2][8][4];
    gemm_mainloop(A, B, 2048, smem, cx, acc);

    const float QSCALE = 0.08838834764831845f;  // 1/sqrt(128)
    const int region = (cx.bn < 2048) ? 0 : (cx.bn < 2560 ? 1 : 2);   // uniform per CTA

#pragma unroll
    for (int mf = 0; mf < 2; mf++) {
#pragma unroll
        for (int rr = 0; rr < 2; rr++) {
            const int row = cx.bm + cx.warpM + mf * 16 + cx.g + rr * 8;
            const int b = row >> 11, s = row & 2047;
            const int a0 = rr * 2;   // acc idx for (col, col+1)
#pragma unroll
            for (int nf = 0; nf < 8; nf++) {
                const int col = cx.bn + cx.warpN + nf * 8 + cx.tg * 2;
                const float x0 = acc[mf][nf][a0], x1 = acc[mf][nf][a0 + 1];
                if (region == 2) {
                    *reinterpret_cast<float2*>(&Cv[(size_t)row * 3072 + col]) =
                        make_float2(x0, x1);
                } else {
                    int cc = (region == 0) ? col : col - 2048;
                    const int h = cc >> 7, d = cc & 127;
                    float2 cs = *reinterpret_cast<const float2*>(&fc[(size_t)s * 128 + d]);
                    float sc = (region == 0) ? QSCALE : 1.0f;
                    float ox = (x0 * cs.x - x1 * cs.y) * sc;
                    float oy = (x0 * cs.y + x1 * cs.x) * sc;
                    __nv_bfloat16 hx = __float2bfloat16(ox), hy = __float2bfloat16(oy);
                    uint32_t ph = (uint32_t)__bfloat16_as_ushort(hx) |
                                  ((uint32_t)__bfloat16_as_ushort(hy) << 16);
                    uint32_t pl = pack_bf16(ox - __bfloat162float(hx),
                                            oy - __bfloat162float(hy));
                    if (region == 0) {
                        size_t addr = ((size_t)(b * HH + h) * SS + s) * HDD + d;
                        *reinterpret_cast<uint32_t*>(qh + addr) = ph;
                        *reinterpret_cast<uint32_t*>(ql + addr) = pl;
                    } else {
                        size_t addr = ((size_t)(b * KVHH + h) * SS + s) * HDD + d;
                        *reinterpret_cast<uint32_t*>(kh + addr) = ph;
                        *reinterpret_cast<uint32_t*>(kl + addr) = pl;
                    }
                }
            }
        }
    }
}

// ---------------------------------------------------------------------------
// V transpose + split: g_qkv V section [b,s][kvh,d] -> Vt hi/lo [b,kvh][d][s]
// ---------------------------------------------------------------------------
__global__ void vt_kernel(const float* __restrict__ qkv,
                          __nv_bfloat16* __restrict__ vth, __nv_bfloat16* __restrict__ vtl)
{
    __shared__ float t[32][33];
    const int s0 = blockIdx.x * 32, d0 = blockIdx.y * 32;
    const int bk = blockIdx.z;            // b*4 + kvh
    const int b = bk >> 2, kvh = bk & 3;
    const int tx = threadIdx.x, ty = threadIdx.y;
#pragma unroll
    for (int j = 0; j < 4; j++) {
        int s = s0 + ty + j * 8;
        t[ty + j * 8][tx] = qkv[((size_t)(b * 2048 + s)) * 3072 + 2560 + kvh * 128 + d0 + tx];
    }
    __syncthreads();
#pragma unroll
    for (int j = 0; j < 4; j++) {
        int d = d0 + ty + j * 8;
        float v = t[tx][ty + j * 8];
        __nv_bfloat16 h = __float2bfloat16(v);
        size_t o = ((size_t)bk * 128 + d) * 2048 + s0 + tx;
        vth[o] = h;
        vtl[o] = __float2bfloat16(v - __bfloat162float(h));
    }
}

// ---------------------------------------------------------------------------
// Tensor-core flash attention — EXACT round-11 measured-good version.
// Split-bf16 (3-term) MMAs, BM=BN=64, 128 threads, single K buf + single V buf
// alternating pipeline; fp16 attn-out epilogue.
// ---------------------------------------------------------------------------
#define FT_KH 0
#define FT_KL 17408
#define FT_VH 34816
#define FT_VL 53248
#define FT_SMEM 71680

__global__ __launch_bounds__(128)
void flash_tc_kernel(const __nv_bfloat16* __restrict__ qh_g, const __nv_bfloat16* __restrict__ ql_g,
                     const __nv_bfloat16* __restrict__ kh_g, const __nv_bfloat16* __restrict__ kl_g,
                     const __nv_bfloat16* __restrict__ vth_g, const __nv_bfloat16* __restrict__ vtl_g,
                     __half* __restrict__ ao)
{
    extern __shared__ __align__(16) char smem[];
    const uint32_t sb = s2u(smem);
    const int tid = threadIdx.x, lane = tid & 31, wm = tid >> 5;
    const int g = lane >> 2, tg = lane & 3;
    const int qb = 31 - (int)blockIdx.x;
    const int bh = blockIdx.y;
    const int b = bh >> 4, h = bh & 15, kvh = h >> 2;

    const __nv_bfloat16* qbh = qh_g + ((size_t)(b * HH + h) * SS + qb * 64 + wm * 16) * HDD;
    const __nv_bfloat16* qbl = ql_g + ((size_t)(b * HH + h) * SS + qb * 64 + wm * 16) * HDD;
    uint32_t qfh[8][4], qfl[8][4];
#pragma unroll
    for (int kf = 0; kf < 8; kf++) {
        size_t o0 = (size_t)g * 128 + kf * 16 + tg * 2;
        qfh[kf][0] = *(const uint32_t*)(qbh + o0);
        qfh[kf][1] = *(const uint32_t*)(qbh + o0 + 8 * 128);
        qfh[kf][2] = *(const uint32_t*)(qbh + o0 + 8);
        qfh[kf][3] = *(const uint32_t*)(qbh + o0 + 8 * 128 + 8);
        qfl[kf][0] = *(const uint32_t*)(qbl + o0);
        qfl[kf][1] = *(const uint32_t*)(qbl + o0 + 8 * 128);
        qfl[kf][2] = *(const uint32_t*)(qbl + o0 + 8);
        qfl[kf][3] = *(const uint32_t*)(qbl + o0 + 8 * 128 + 8);
    }

    const size_t kvbase = (size_t)(b * KVHH + kvh) * SS * HDD;

    auto load_K = [&](int kt) {
        const char* sh = (const char*)(kh_g + kvbase + (size_t)kt * 64 * 128);
        const char* sl = (const char*)(kl_g + kvbase + (size_t)kt * 64 * 128);
#pragma unroll
        for (int i = 0; i < 8; i++) {
            int c = tid + i * 128;
            int key = c >> 4, q = c & 15;
            CP_ASYNC16(sb + FT_KH + key * 272 + q * 16, sh + key * 256 + q * 16);
            CP_ASYNC16(sb + FT_KL + key * 272 + q * 16, sl + key * 256 + q * 16);
        }
    };
    auto load_V = [&](int kt) {
        const size_t vb = (size_t)(b * KVHH + kvh) * HDD * SS + (size_t)kt * 64;
#pragma unroll
        for (int i = 0; i < 8; i++) {
            int c = tid + i * 128;
            int d = c >> 3, q = c & 7;
            const char* sh = (const char*)(vth_g + vb + (size_t)d * 2048) + q * 16;
            const char* sl = (const char*)(vtl_g + vb + (size_t)d * 2048) + q * 16;
            CP_ASYNC16(sb + FT_VH + d * 144 + q * 16, sh);
            CP_ASYNC16(sb + FT_VL + d * 144 + q * 16, sl);
        }
    };

    float of[16][4];
#pragma unroll
    for (int i = 0; i < 16; i++)
#pragma unroll
        for (int r = 0; r < 4; r++) of[i][r] = 0.0f;
    float m0 = -1e30f, m1 = -1e30f, l0 = 0.0f, l1 = 0.0f;

    const int nt = qb + 1;
    load_K(0); CP_COMMIT();

    for (int kt = 0; kt < nt; kt++) {
        CP_WAIT(0);
        __syncthreads();
        load_V(kt); CP_COMMIT();

        float sacc[8][4];
#pragma unroll
        for (int nf = 0; nf < 8; nf++)
#pragma unroll
            for (int r = 0; r < 4; r++) sacc[nf][r] = 0.0f;

#pragma unroll
        for (int kf = 0; kf < 8; kf++) {
#pragma unroll
            for (int nf = 0; nf < 8; nf++) {
                const int ko = FT_KH + (nf * 8 + g) * 272 + kf * 32 + tg * 4;
                uint32_t bhf[2], blf[2];
                bhf[0] = *(const uint32_t*)(smem + ko);
                bhf[1] = *(const uint32_t*)(smem + ko + 16);
                blf[0] = *(const uint32_t*)(smem + ko + (FT_KL - FT_KH));
                blf[1] = *(const uint32_t*)(smem + ko + (FT_KL - FT_KH) + 16);
                MMA_BF16(sacc[nf], qfh[kf], bhf);
                MMA_BF16(sacc[nf], qfh[kf], blf);
                MMA_BF16(sacc[nf], qfl[kf], bhf);
            }
        }

        CP_WAIT(0);
        __syncthreads();
        if (kt + 1 < nt) { load_K(kt + 1); CP_COMMIT(); }

        if (kt == qb) {
            const int r0 = wm * 16 + g, r1 = r0 + 8;
#pragma unroll
            for (int nf = 0; nf < 8; nf++) {
                const int c0 = nf * 8 + tg * 2;
                if (c0     > r0) sacc[nf][0] = -1e30f;
                if (c0 + 1 > r0) sacc[nf][1] = -1e30f;
                if (c0     > r1) sacc[nf][2] = -1e30f;
                if (c0 + 1 > r1) sacc[nf][3] = -1e30f;
            }
        }

        float mx0 = -1e30f, mx1 = -1e30f;
#pragma unroll
        for (int nf = 0; nf < 8; nf++) {
            mx0 = fmaxf(mx0, fmaxf(sacc[nf][0], sacc[nf][1]));
            mx1 = fmaxf(mx1, fmaxf(sacc[nf][2], sacc[nf][3]));
        }
        mx0 = fmaxf(mx0, __shfl_xor_sync(0xffffffffu, mx0, 1));
        mx0 = fmaxf(mx0, __shfl_xor_sync(0xffffffffu, mx0, 2));
        mx1 = fmaxf(mx1, __shfl_xor_sync(0xffffffffu, mx1, 1));
        mx1 = fmaxf(mx1, __shfl_xor_sync(0xffffffffu, mx1, 2));
        const float mn0 = fmaxf(m0, mx0), mn1 = fmaxf(m1, mx1);
        const float al0 = __expf(m0 - mn0), al1 = __expf(m1 - mn1);

        uint32_t paH[4][4], paL[4][4];
        float rs0 = 0.0f, rs1 = 0.0f;
#pragma unroll
        for (int nf = 0; nf < 8; nf++) {
            float p0 = __expf(sacc[nf][0] - mn0);
            float p1 = __expf(sacc[nf][1] - mn0);
            float p2 = __expf(sacc[nf][2] - mn1);
            float p3 = __expf(sacc[nf][3] - mn1);
            rs0 += p0 + p1;
            rs1 += p2 + p3;
            __nv_bfloat16 h0 = __float2bfloat16(p0), h1 = __float2bfloat16(p1);
            __nv_bfloat16 h2 = __float2bfloat16(p2), h3 = __float2bfloat16(p3);
            const int kfp = nf >> 1, o = (nf & 1) * 2;
            paH[kfp][o]     = (uint32_t)__bfloat16_as_ushort(h0) |
                              ((uint32_t)__bfloat16_as_ushort(h1) << 16);
            paH[kfp][o + 1] = (uint32_t)__bfloat16_as_ushort(h2) |
                              ((uint32_t)__bfloat16_as_ushort(h3) << 16);
            paL[kfp][o]     = pack_bf16(p0 - __bfloat162float(h0), p1 - __bfloat162float(h1));
            paL[kfp][o + 1] = pack_bf16(p2 - __bfloat162float(h2), p3 - __bfloat162float(h3));
        }
        rs0 += __shfl_xor_sync(0xffffffffu, rs0, 1);
        rs0 += __shfl_xor_sync(0xffffffffu, rs0, 2);
        rs1 += __shfl_xor_sync(0xffffffffu, rs1, 1);
        rs1 += __shfl_xor_sync(0xffffffffu, rs1, 2);
        l0 = l0 * al0 + rs0;
        l1 = l1 * al1 + rs1;
        m0 = mn0; m1 = mn1;
#pragma unroll
        for (int nfo = 0; nfo < 16; nfo++) {
            of[nfo][0] *= al0; of[nfo][1] *= al0;
            of[nfo][2] *= al1; of[nfo][3] *= al1;
        }

#pragma unroll
        for (int kfp = 0; kfp < 4; kfp++) {
#pragma unroll
            for (int nfo = 0; nfo < 16; nfo++) {
                const int vo = FT_VH + (nfo * 8 + g) * 144 + kfp * 32 + tg * 4;
                uint32_t vh[2], vl[2];
                vh[0] = *(const uint32_t*)(smem + vo);
                vh[1] = *(const uint32_t*)(smem + vo + 16);
                vl[0] = *(const uint32_t*)(smem + vo + (FT_VL - FT_VH));
                vl[1] = *(const uint32_t*)(smem + vo + (FT_VL - FT_VH) + 16);
                MMA_BF16(of[nfo], paH[kfp], vh);
                MMA_BF16(of[nfo], paH[kfp], vl);
                MMA_BF16(of[nfo], paL[kfp], vh);
            }
        }
    }

    const float inv0 = 1.0f / l0, inv1 = 1.0f / l1;
    const int row0 = b * SS + qb * 64 + wm * 16 + g;
    const size_t base0 = (size_t)row0 * (HH * HDD) + (size_t)h * HDD;
    const size_t base1 = base0 + (size_t)8 * (HH * HDD);
#pragma unroll
    for (int nfo = 0; nfo < 16; nfo++) {
        const int col = nfo * 8 + tg * 2;
        *reinterpret_cast<uint32_t*>(ao + base0 + col) =
            pack_h(of[nfo][0] * inv0, of[nfo][1] * inv0);
        *reinterpret_cast<uint32_t*>(ao + base1 + col) =
            pack_h(of[nfo][2] * inv1, of[nfo][3] * inv1);
    }
}

// ---------------------------------------------------------------------------
// Host launcher
// ---------------------------------------------------------------------------
extern "C" void kernel_launch(void* const* d_in, const int* in_sizes, int n_in,
                              void* d_out, int out_size)
{
    (void)in_sizes; (void)n_in; (void)out_size;
    const float* x  = (const float*)d_in[0];
    const float* fc = (const float*)d_in[1];
    const float* wq = (const float*)d_in[2];
    const float* wk = (const float*)d_in[3];
    const float* wv = (const float*)d_in[4];
    const float* wo = (const float*)d_in[5];
    float* out = (float*)d_out;

    float* pqkv;
    __half *pxh, *pwh, *pao, *pwoh;
    __nv_bfloat16 *pqh, *pql, *pkh, *pkl, *pvth, *pvtl;
    cudaGetSymbolAddress((void**)&pqkv, g_qkv);
    cudaGetSymbolAddress((void**)&pxh,  g_xh);
    cudaGetSymbolAddress((void**)&pwh,  g_wh);
    cudaGetSymbolAddress((void**)&pao,  g_ao);
    cudaGetSymbolAddress((void**)&pwoh, g_woh);
    cudaGetSymbolAddress((void**)&pqh,  g_qh);
    cudaGetSymbolAddress((void**)&pql,  g_ql);
    cudaGetSymbolAddress((void**)&pkh,  g_kh);
    cudaGetSymbolAddress((void**)&pkl,  g_kl);
    cudaGetSymbolAddress((void**)&pvth, g_vth);
    cudaGetSymbolAddress((void**)&pvtl, g_vtl);

    cudaFuncSetAttribute(tc_gemm_f16_kernel, cudaFuncAttributeMaxDynamicSharedMemorySize,
                         GEMM_SMEM);
    cudaFuncSetAttribute(tc_gemm_qkv_kernel, cudaFuncAttributeMaxDynamicSharedMemorySize,
                         GEMM_SMEM);
    cudaFuncSetAttribute(flash_tc_kernel, cudaFuncAttributeMaxDynamicSharedMemorySize, FT_SMEM);

    // fp32 -> fp16 converts
    {
        long n4 = (long)4096 * 2048 / 4;
        cvt_h_kernel<<<(unsigned)((n4 + 255) / 256), 256>>>(x, pxh, n4);
    }
    {
        long n4 = (long)2048 * 2048 / 4;
        cvt_h_kernel<<<(unsigned)((n4 + 255) / 256), 256>>>(wq, pwh, n4);
    }
    {
        long n4 = (long)512 * 2048 / 4;
        cvt_h_kernel<<<(unsigned)((n4 + 255) / 256), 256>>>(wk, pwh + (size_t)2048 * 2048, n4);
        cvt_h_kernel<<<(unsigned)((n4 + 255) / 256), 256>>>(wv, pwh + (size_t)2560 * 2048, n4);
    }

    // QKV projection with fused RoPE epilogue
    tc_gemm_qkv_kernel<<<dim3(3072 / GBN, 4096 / GBM), 256, GEMM_SMEM>>>(
        pxh, pwh, fc, pqkv, pqh, pql, pkh, pkl);

    // V transpose -> Vt bf16 hi/lo
    vt_kernel<<<dim3(64, 4, 8), dim3(32, 8)>>>(pqkv, pvth, pvtl);

    // Tensor-core flash attention (split-bf16, measured-good) -> attn out fp16
    flash_tc_kernel<<<dim3(32, 32), 128, FT_SMEM>>>(pqh, pql, pkh, pkl, pvth, pvtl, pao);

    // wo projection (fp16): [4096,2048] x [2048,2048]^T -> out
    {
        long n4 = (long)2048 * 2048 / 4;
        cvt_h_kernel<<<(unsigned)((n4 + 255) / 256), 256>>>(wo, pwoh, n4);
    }
    tc_gemm_f16_kernel<<<dim3(2048 / GBN, 4096 / GBM), 256, GEMM_SMEM>>>(
        pao, pwoh, out, 2048, 2048);
}

// round 16
// speedup vs baseline: 1.2825x; 1.0784x over previous
#include <cuda_runtime.h>
#include <cuda_bf16.h>
#include <cuda_fp16.h>
#include <cstdint>
#include <cstddef>

// Problem constants
#define BB   2
#define SS   2048
#define DIMM 2048
#define HH   16
#define KVHH 4
#define HDD  128
// M = B*S = 4096, QKV N = 3072, K = 2048

// ---------------------------------------------------------------------------
// Scratch (static device globals; no allocation anywhere)
// ---------------------------------------------------------------------------
__device__ float  g_qkv[(size_t)4096 * 3072];           // only V cols [2560,3072) written
__device__ __half g_xh [(size_t)4096 * 2048];           // x fp16
__device__ __half g_wh [(size_t)3072 * 2048];           // concat [wq;wk;wv] fp16
__device__ __half g_ao [(size_t)4096 * 2048];           // attn out fp16 (flash writes)
__device__ __half g_woh[(size_t)2048 * 2048];           // wo fp16

// flash operands, bf16 hi/lo (split — measured-good accuracy hedge)
__device__ __nv_bfloat16 g_qh [(size_t)BB * HH  * SS * HDD];  // roped+scaled
__device__ __nv_bfloat16 g_ql [(size_t)BB * HH  * SS * HDD];
__device__ __nv_bfloat16 g_kh [(size_t)BB * KVHH * SS * HDD]; // roped
__device__ __nv_bfloat16 g_kl [(size_t)BB * KVHH * SS * HDD];
__device__ __nv_bfloat16 g_vth[(size_t)BB * KVHH * HDD * SS]; // [b][kvh][d][s]
__device__ __nv_bfloat16 g_vtl[(size_t)BB * KVHH * HDD * SS];

// ---------------------------------------------------------------------------
// PTX helpers (sm_80+ baseline: cp.async + mma.sync + ldmatrix)
// ---------------------------------------------------------------------------
__device__ __forceinline__ uint32_t s2u(const void* p) {
    uint32_t a;
    asm("{ .reg .u64 t; cvta.to.shared.u64 t, %1; cvt.u32.u64 %0, t; }" : "=r"(a) : "l"(p));
    return a;
}

#define CP_ASYNC16(dst, src) \
    asm volatile("cp.async.cg.shared.global [%0], [%1], 16;" :: "r"(dst), "l"(src) : "memory")
#define CP_COMMIT() asm volatile("cp.async.commit_group;" ::: "memory")
#define CP_WAIT(n)  asm volatile("cp.async.wait_group %0;" :: "n"(n) : "memory")

#define MMA_BF16(acc, a, b) \
    asm volatile("mma.sync.aligned.m16n8k16.row.col.f32.bf16.bf16.f32 " \
                 "{%0,%1,%2,%3}, {%4,%5,%6,%7}, {%8,%9}, {%0,%1,%2,%3};" \
                 : "+f"((acc)[0]), "+f"((acc)[1]), "+f"((acc)[2]), "+f"((acc)[3]) \
                 : "r"((a)[0]), "r"((a)[1]), "r"((a)[2]), "r"((a)[3]), \
                   "r"((b)[0]), "r"((b)[1]))

#define MMA_F16(acc, a, b) \
    asm volatile("mma.sync.aligned.m16n8k16.row.col.f32.f16.f16.f32 " \
                 "{%0,%1,%2,%3}, {%4,%5,%6,%7}, {%8,%9}, {%0,%1,%2,%3};" \
                 : "+f"((acc)[0]), "+f"((acc)[1]), "+f"((acc)[2]), "+f"((acc)[3]) \
                 : "r"((a)[0]), "r"((a)[1]), "r"((a)[2]), "r"((a)[3]), \
                   "r"((b)[0]), "r"((b)[1]))

// ldmatrix x4: loads four 8x8 b16 matrices; matrix j's 8 row addresses come
// from lanes j*8..j*8+7; result matrix j lands in reg j with the mma fragment
// lane mapping (lane g*4+tg holds row g, cols 2tg,2tg+1).
#define LDSM_X4(r0, r1, r2, r3, addr) \
    asm volatile("ldmatrix.sync.aligned.m8n8.x4.shared.b16 {%0,%1,%2,%3}, [%4];" \
                 : "=r"(r0), "=r"(r1), "=r"(r2), "=r"(r3) : "r"(addr))

__device__ __forceinline__ uint32_t pack_bf16(float a, float b) {
    uint32_t lo = __bfloat16_as_ushort(__float2bfloat16(a));
    uint32_t hi = __bfloat16_as_ushort(__float2bfloat16(b));
    return lo | (hi << 16);
}
__device__ __forceinline__ uint32_t pack_h(float a, float b) {
    __half2 h = __floats2half2_rn(a, b);
    return *reinterpret_cast<uint32_t*>(&h);
}

// ---------------------------------------------------------------------------
// fp32 -> fp16 convert (float4 per thread)
// ---------------------------------------------------------------------------
__global__ void cvt_h_kernel(const float* __restrict__ src, __half* __restrict__ dst, long n4)
{
    long i = (long)blockIdx.x * blockDim.x + threadIdx.x;
    if (i >= n4) return;
    float4 v = reinterpret_cast<const float4*>(src)[i];
    uint2 o;
    o.x = pack_h(v.x, v.y);
    o.y = pack_h(v.z, v.w);
    *reinterpret_cast<uint2*>(dst + i * 4) = o;
}

// ---------------------------------------------------------------------------
// Shared GEMM guts: mma.sync fp16, tile 128x128, BK=32, 3-stage cp.async,
// fragments via ldmatrix.x4 (conflict-free on 80B row stride).
// ---------------------------------------------------------------------------
#define GBM 128
#define GBN 128
#define GBK 32
#define TILE_BYTES  (128 * 80)
#define STAGE_BYTES (2 * TILE_BYTES)        // A | B
#define NSTAGE 3
#define GEMM_SMEM (NSTAGE * STAGE_BYTES)    // 61440 B

struct GemmCtx {
    int tid, lane, wid, g, tg, warpM, warpN, bm, bn;
};

__device__ __forceinline__ void gemm_mainloop(
    const __half* __restrict__ A, const __half* __restrict__ B,
    int K, char* smem, const GemmCtx& cx, float acc[2][8][4])
{
    const uint32_t smem_u = s2u(smem);
    const int nchunk = K / GBK;
    const int mat = cx.lane >> 3, rowin = cx.lane & 7;

#pragma unroll
    for (int mf = 0; mf < 2; mf++)
#pragma unroll
        for (int nf = 0; nf < 8; nf++)
#pragma unroll
            for (int r = 0; r < 4; r++) acc[mf][nf][r] = 0.0f;

    auto load_stage = [&](int s, int c) {
        const int k0 = c * GBK;
        const uint32_t stg = smem_u + (uint32_t)s * STAGE_BYTES;
#pragma unroll
        for (int i = 0; i < 4; i++) {
            int f = cx.tid + i * 256;
            int tile = f >> 9;
            int fi = f & 511;
            int r = fi >> 2, q = fi & 3;
            const __half* src = (tile == 0) ? A + (size_t)(cx.bm + r) * K + k0 + q * 8
                                            : B + (size_t)(cx.bn + r) * K + k0 + q * 8;
            uint32_t dst = stg + (uint32_t)tile * TILE_BYTES + (uint32_t)r * 80 + q * 16;
            CP_ASYNC16(dst, src);
        }
    };

    auto compute_stage = [&](int s) {
        const uint32_t stgu = smem_u + (uint32_t)s * STAGE_BYTES;
        const uint32_t pAu = stgu;
        const uint32_t pBu = stgu + TILE_BYTES;
#pragma unroll
        for (int ks = 0; ks < 2; ks++) {
            const int cb = ks * 32;
            uint32_t a[2][4], b[8][2];
            // A fragments: matrices (0,0),(8,0),(0,8),(8,8) -> regs 0..3
#pragma unroll
            for (int mf = 0; mf < 2; mf++) {
                uint32_t addr = pAu +
                    (uint32_t)(cx.warpM + mf * 16 + (mat & 1) * 8 + rowin) * 80 +
                    cb + (mat >> 1) * 16;
                LDSM_X4(a[mf][0], a[mf][1], a[mf][2], a[mf][3], addr);
            }
            // B fragments: (b[2np][0], b[2np][1], b[2np+1][0], b[2np+1][1])
#pragma unroll
            for (int np = 0; np < 4; np++) {
                uint32_t addr = pBu +
                    (uint32_t)(cx.warpN + np * 16 + (mat >> 1) * 8 + rowin) * 80 +
                    cb + (mat & 1) * 16;
                LDSM_X4(b[np * 2][0], b[np * 2][1], b[np * 2 + 1][0], b[np * 2 + 1][1], addr);
            }
#pragma unroll
            for (int mf = 0; mf < 2; mf++)
#pragma unroll
                for (int nf = 0; nf < 8; nf++)
                    MMA_F16(acc[mf][nf], a[mf], b[nf]);
        }
    };

    load_stage(0, 0); CP_COMMIT();
    load_stage(1, 1); CP_COMMIT();

    for (int c = 0; c < nchunk; ++c) {
        if (c + 2 < nchunk) { CP_WAIT(1); } else { CP_WAIT(0); }
        __syncthreads();
        if (c + 2 < nchunk) {
            load_stage((c + 2) % NSTAGE, c + 2);
            CP_COMMIT();
        }
        compute_stage(c % NSTAGE);
        __syncthreads();
    }
}

// ---------------------------------------------------------------------------
// Plain fp16 GEMM -> fp32 C  (wo projection)
// ---------------------------------------------------------------------------
__global__ __launch_bounds__(256)
void tc_gemm_f16_kernel(const __half* __restrict__ A, const __half* __restrict__ B,
                        float* __restrict__ C, int N, int K)
{
    extern __shared__ __align__(16) char smem[];
    GemmCtx cx;
    cx.tid = threadIdx.x; cx.lane = cx.tid & 31; cx.wid = cx.tid >> 5;
    cx.g = cx.lane >> 2; cx.tg = cx.lane & 3;
    cx.warpM = (cx.wid >> 1) * 32; cx.warpN = (cx.wid & 1) * 64;
    cx.bm = blockIdx.y * GBM; cx.bn = blockIdx.x * GBN;

    float acc[2][8][4];
    gemm_mainloop(A, B, K, smem, cx, acc);

#pragma unroll
    for (int mf = 0; mf < 2; mf++) {
        const int row0 = cx.bm + cx.warpM + mf * 16 + cx.g;
#pragma unroll
        for (int nf = 0; nf < 8; nf++) {
            const int col = cx.bn + cx.warpN + nf * 8 + cx.tg * 2;
            float2 v0 = make_float2(acc[mf][nf][0], acc[mf][nf][1]);
            float2 v1 = make_float2(acc[mf][nf][2], acc[mf][nf][3]);
            *reinterpret_cast<float2*>(&C[(size_t)row0 * N + col]) = v0;
            *reinterpret_cast<float2*>(&C[(size_t)(row0 + 8) * N + col]) = v1;
        }
    }
}

// ---------------------------------------------------------------------------
// QKV GEMM with fused RoPE epilogue (unchanged from R15).
// ---------------------------------------------------------------------------
__global__ __launch_bounds__(256)
void tc_gemm_qkv_kernel(const __half* __restrict__ A, const __half* __restrict__ B,
                        const float* __restrict__ fc,
                        float* __restrict__ Cv,
                        __nv_bfloat16* __restrict__ qh, __nv_bfloat16* __restrict__ ql,
                        __nv_bfloat16* __restrict__ kh, __nv_bfloat16* __restrict__ kl)
{
    extern __shared__ __align__(16) char smem[];
    GemmCtx cx;
    cx.tid = threadIdx.x; cx.lane = cx.tid & 31; cx.wid = cx.tid >> 5;
    cx.g = cx.lane >> 2; cx.tg = cx.lane & 3;
    cx.warpM = (cx.wid >> 1) * 32; cx.warpN = (cx.wid & 1) * 64;
    cx.bm = blockIdx.y * GBM; cx.bn = blockIdx.x * GBN;

    float acc[2][8][4];
    gemm_mainloop(A, B, 2048, smem, cx, acc);

    const float QSCALE = 0.08838834764831845f;  // 1/sqrt(128)
    const int region = (cx.bn < 2048) ? 0 : (cx.bn < 2560 ? 1 : 2);   // uniform per CTA

#pragma unroll
    for (int mf = 0; mf < 2; mf++) {
#pragma unroll
        for (int rr = 0; rr < 2; rr++) {
            const int row = cx.bm + cx.warpM + mf * 16 + cx.g + rr * 8;
            const int b = row >> 11, s = row & 2047;
            const int a0 = rr * 2;
#pragma unroll
            for (int nf = 0; nf < 8; nf++) {
                const int col = cx.bn + cx.warpN + nf * 8 + cx.tg * 2;
                const float x0 = acc[mf][nf][a0], x1 = acc[mf][nf][a0 + 1];
                if (region == 2) {
                    *reinterpret_cast<float2*>(&Cv[(size_t)row * 3072 + col]) =
                        make_float2(x0, x1);
                } else {
                    int cc = (region == 0) ? col : col - 2048;
                    const int h = cc >> 7, d = cc & 127;
                    float2 cs = *reinterpret_cast<const float2*>(&fc[(size_t)s * 128 + d]);
                    float sc = (region == 0) ? QSCALE : 1.0f;
                    float ox = (x0 * cs.x - x1 * cs.y) * sc;
                    float oy = (x0 * cs.y + x1 * cs.x) * sc;
                    __nv_bfloat16 hx = __float2bfloat16(ox), hy = __float2bfloat16(oy);
                    uint32_t ph = (uint32_t)__bfloat16_as_ushort(hx) |
                                  ((uint32_t)__bfloat16_as_ushort(hy) << 16);
                    uint32_t pl = pack_bf16(ox - __bfloat162float(hx),
                                            oy - __bfloat162float(hy));
                    if (region == 0) {
                        size_t addr = ((size_t)(b * HH + h) * SS + s) * HDD + d;
                        *reinterpret_cast<uint32_t*>(qh + addr) = ph;
                        *reinterpret_cast<uint32_t*>(ql + addr) = pl;
                    } else {
                        size_t addr = ((size_t)(b * KVHH + h) * SS + s) * HDD + d;
                        *reinterpret_cast<uint32_t*>(kh + addr) = ph;
                        *reinterpret_cast<uint32_t*>(kl + addr) = pl;
                    }
                }
            }
        }
    }
}

// ---------------------------------------------------------------------------
// V transpose + split: g_qkv V section [b,s][kvh,d] -> Vt hi/lo [b,kvh][d][s]
// ---------------------------------------------------------------------------
__global__ void vt_kernel(const float* __restrict__ qkv,
                          __nv_bfloat16* __restrict__ vth, __nv_bfloat16* __restrict__ vtl)
{
    __shared__ float t[32][33];
    const int s0 = blockIdx.x * 32, d0 = blockIdx.y * 32;
    const int bk = blockIdx.z;            // b*4 + kvh
    const int b = bk >> 2, kvh = bk & 3;
    const int tx = threadIdx.x, ty = threadIdx.y;
#pragma unroll
    for (int j = 0; j < 4; j++) {
        int s = s0 + ty + j * 8;
        t[ty + j * 8][tx] = qkv[((size_t)(b * 2048 + s)) * 3072 + 2560 + kvh * 128 + d0 + tx];
    }
    __syncthreads();
#pragma unroll
    for (int j = 0; j < 4; j++) {
        int d = d0 + ty + j * 8;
        float v = t[tx][ty + j * 8];
        __nv_bfloat16 h = __float2bfloat16(v);
        size_t o = ((size_t)bk * 128 + d) * 2048 + s0 + tx;
        vth[o] = h;
        vtl[o] = __float2bfloat16(v - __bfloat162float(h));
    }
}

// ---------------------------------------------------------------------------
// Tensor-core flash attention — split-bf16 3-term, with ldmatrix fragment
// loads (K stride 272B, V stride 144B: both conflict-free).
// ---------------------------------------------------------------------------
#define FT_KH 0
#define FT_KL 17408
#define FT_VH 34816
#define FT_VL 53248
#define FT_SMEM 71680

__global__ __launch_bounds__(128)
void flash_tc_kernel(const __nv_bfloat16* __restrict__ qh_g, const __nv_bfloat16* __restrict__ ql_g,
                     const __nv_bfloat16* __restrict__ kh_g, const __nv_bfloat16* __restrict__ kl_g,
                     const __nv_bfloat16* __restrict__ vth_g, const __nv_bfloat16* __restrict__ vtl_g,
                     __half* __restrict__ ao)
{
    extern __shared__ __align__(16) char smem[];
    const uint32_t sb = s2u(smem);
    const int tid = threadIdx.x, lane = tid & 31, wm = tid >> 5;
    const int g = lane >> 2, tg = lane & 3;
    const int mat = lane >> 3, rowin = lane & 7;
    const int qb = 31 - (int)blockIdx.x;
    const int bh = blockIdx.y;
    const int b = bh >> 4, h = bh & 15, kvh = h >> 2;

    const __nv_bfloat16* qbh = qh_g + ((size_t)(b * HH + h) * SS + qb * 64 + wm * 16) * HDD;
    const __nv_bfloat16* qbl = ql_g + ((size_t)(b * HH + h) * SS + qb * 64 + wm * 16) * HDD;
    uint32_t qfh[8][4], qfl[8][4];
#pragma unroll
    for (int kf = 0; kf < 8; kf++) {
        size_t o0 = (size_t)g * 128 + kf * 16 + tg * 2;
        qfh[kf][0] = *(const uint32_t*)(qbh + o0);
        qfh[kf][1] = *(const uint32_t*)(qbh + o0 + 8 * 128);
        qfh[kf][2] = *(const uint32_t*)(qbh + o0 + 8);
        qfh[kf][3] = *(const uint32_t*)(qbh + o0 + 8 * 128 + 8);
        qfl[kf][0] = *(const uint32_t*)(qbl + o0);
        qfl[kf][1] = *(const uint32_t*)(qbl + o0 + 8 * 128);
        qfl[kf][2] = *(const uint32_t*)(qbl + o0 + 8);
        qfl[kf][3] = *(const uint32_t*)(qbl + o0 + 8 * 128 + 8);
    }

    const size_t kvbase = (size_t)(b * KVHH + kvh) * SS * HDD;

    auto load_K = [&](int kt) {
        const char* sh = (const char*)(kh_g + kvbase + (size_t)kt * 64 * 128);
        const char* sl = (const char*)(kl_g + kvbase + (size_t)kt * 64 * 128);
#pragma unroll
        for (int i = 0; i < 8; i++) {
            int c = tid + i * 128;
            int key = c >> 4, q = c & 15;
            CP_ASYNC16(sb + FT_KH + key * 272 + q * 16, sh + key * 256 + q * 16);
            CP_ASYNC16(sb + FT_KL + key * 272 + q * 16, sl + key * 256 + q * 16);
        }
    };
    auto load_V = [&](int kt) {
        const size_t vb = (size_t)(b * KVHH + kvh) * HDD * SS + (size_t)kt * 64;
#pragma unroll
        for (int i = 0; i < 8; i++) {
            int c = tid + i * 128;
            int d = c >> 3, q = c & 7;
            const char* sh = (const char*)(vth_g + vb + (size_t)d * 2048) + q * 16;
            const char* sl = (const char*)(vtl_g + vb + (size_t)d * 2048) + q * 16;
            CP_ASYNC16(sb + FT_VH + d * 144 + q * 16, sh);
            CP_ASYNC16(sb + FT_VL + d * 144 + q * 16, sl);
        }
    };

    float of[16][4];
#pragma unroll
    for (int i = 0; i < 16; i++)
#pragma unroll
        for (int r = 0; r < 4; r++) of[i][r] = 0.0f;
    float m0 = -1e30f, m1 = -1e30f, l0 = 0.0f, l1 = 0.0f;

    const int nt = qb + 1;
    load_K(0); CP_COMMIT();

    for (int kt = 0; kt < nt; kt++) {
        CP_WAIT(0);
        __syncthreads();
        load_V(kt); CP_COMMIT();

        float sacc[8][4];
#pragma unroll
        for (int nf = 0; nf < 8; nf++)
#pragma unroll
            for (int r = 0; r < 4; r++) sacc[nf][r] = 0.0f;

        // ---- S = Q K^T (3-term, ldmatrix fragment loads) -----------------
#pragma unroll
        for (int kf = 0; kf < 8; kf++) {
#pragma unroll
            for (int np = 0; np < 4; np++) {
                const uint32_t kaddr = sb + FT_KH +
                    (uint32_t)(np * 16 + (mat >> 1) * 8 + rowin) * 272 +
                    kf * 32 + (mat & 1) * 16;
                uint32_t bhf[4], blf[4];
                LDSM_X4(bhf[0], bhf[1], bhf[2], bhf[3], kaddr);
                LDSM_X4(blf[0], blf[1], blf[2], blf[3], kaddr + (FT_KL - FT_KH));
                MMA_BF16(sacc[2 * np],     qfh[kf], bhf);
                MMA_BF16(sacc[2 * np],     qfh[kf], blf);
                MMA_BF16(sacc[2 * np],     qfl[kf], bhf);
                MMA_BF16(sacc[2 * np + 1], qfh[kf], bhf + 2);
                MMA_BF16(sacc[2 * np + 1], qfh[kf], blf + 2);
                MMA_BF16(sacc[2 * np + 1], qfl[kf], bhf + 2);
            }
        }

        CP_WAIT(0);
        __syncthreads();
        if (kt + 1 < nt) { load_K(kt + 1); CP_COMMIT(); }

        if (kt == qb) {
            const int r0 = wm * 16 + g, r1 = r0 + 8;
#pragma unroll
            for (int nf = 0; nf < 8; nf++) {
                const int c0 = nf * 8 + tg * 2;
                if (c0     > r0) sacc[nf][0] = -1e30f;
                if (c0 + 1 > r0) sacc[nf][1] = -1e30f;
                if (c0     > r1) sacc[nf][2] = -1e30f;
                if (c0 + 1 > r1) sacc[nf][3] = -1e30f;
            }
        }

        float mx0 = -1e30f, mx1 = -1e30f;
#pragma unroll
        for (int nf = 0; nf < 8; nf++) {
            mx0 = fmaxf(mx0, fmaxf(sacc[nf][0], sacc[nf][1]));
            mx1 = fmaxf(mx1, fmaxf(sacc[nf][2], sacc[nf][3]));
        }
        mx0 = fmaxf(mx0, __shfl_xor_sync(0xffffffffu, mx0, 1));
        mx0 = fmaxf(mx0, __shfl_xor_sync(0xffffffffu, mx0, 2));
        mx1 = fmaxf(mx1, __shfl_xor_sync(0xffffffffu, mx1, 1));
        mx1 = fmaxf(mx1, __shfl_xor_sync(0xffffffffu, mx1, 2));
        const float mn0 = fmaxf(m0, mx0), mn1 = fmaxf(m1, mx1);
        const float al0 = __expf(m0 - mn0), al1 = __expf(m1 - mn1);

        uint32_t paH[4][4], paL[4][4];
        float rs0 = 0.0f, rs1 = 0.0f;
#pragma unroll
        for (int nf = 0; nf < 8; nf++) {
            float p0 = __expf(sacc[nf][0] - mn0);
            float p1 = __expf(sacc[nf][1] - mn0);
            float p2 = __expf(sacc[nf][2] - mn1);
            float p3 = __expf(sacc[nf][3] - mn1);
            rs0 += p0 + p1;
            rs1 += p2 + p3;
            __nv_bfloat16 h0 = __float2bfloat16(p0), h1 = __float2bfloat16(p1);
            __nv_bfloat16 h2 = __float2bfloat16(p2), h3 = __float2bfloat16(p3);
            const int kfp = nf >> 1, o = (nf & 1) * 2;
            paH[kfp][o]     = (uint32_t)__bfloat16_as_ushort(h0) |
                              ((uint32_t)__bfloat16_as_ushort(h1) << 16);
            paH[kfp][o + 1] = (uint32_t)__bfloat16_as_ushort(h2) |
                              ((uint32_t)__bfloat16_as_ushort(h3) << 16);
            paL[kfp][o]     = pack_bf16(p0 - __bfloat162float(h0), p1 - __bfloat162float(h1));
            paL[kfp][o + 1] = pack_bf16(p2 - __bfloat162float(h2), p3 - __bfloat162float(h3));
        }
        rs0 += __shfl_xor_sync(0xffffffffu, rs0, 1);
        rs0 += __shfl_xor_sync(0xffffffffu, rs0, 2);
        rs1 += __shfl_xor_sync(0xffffffffu, rs1, 1);
        rs1 += __shfl_xor_sync(0xffffffffu, rs1, 2);
        l0 = l0 * al0 + rs0;
        l1 = l1 * al1 + rs1;
        m0 = mn0; m1 = mn1;
#pragma unroll
        for (int nfo = 0; nfo < 16; nfo++) {
            of[nfo][0] *= al0; of[nfo][1] *= al0;
            of[nfo][2] *= al1; of[nfo][3] *= al1;
        }

        // ---- O += P V (3-term, ldmatrix fragment loads) ------------------
#pragma unroll
        for (int kfp = 0; kfp < 4; kfp++) {
#pragma unroll
            for (int np = 0; np < 8; np++) {
                const uint32_t vaddr = sb + FT_VH +
                    (uint32_t)(np * 16 + (mat >> 1) * 8 + rowin) * 144 +
                    kfp * 32 + (mat & 1) * 16;
                uint32_t vh[4], vl[4];
                LDSM_X4(vh[0], vh[1], vh[2], vh[3], vaddr);
                LDSM_X4(vl[0], vl[1], vl[2], vl[3], vaddr + (FT_VL - FT_VH));
                MMA_BF16(of[2 * np],     paH[kfp], vh);
                MMA_BF16(of[2 * np],     paH[kfp], vl);
                MMA_BF16(of[2 * np],     paL[kfp], vh);
                MMA_BF16(of[2 * np + 1], paH[kfp], vh + 2);
                MMA_BF16(of[2 * np + 1], paH[kfp], vl + 2);
                MMA_BF16(of[2 * np + 1], paL[kfp], vh + 2);
            }
        }
    }

    const float inv0 = 1.0f / l0, inv1 = 1.0f / l1;
    const int row0 = b * SS + qb * 64 + wm * 16 + g;
    const size_t base0 = (size_t)row0 * (HH * HDD) + (size_t)h * HDD;
    const size_t base1 = base0 + (size_t)8 * (HH * HDD);
#pragma unroll
    for (int nfo = 0; nfo < 16; nfo++) {
        const int col = nfo * 8 + tg * 2;
        *reinterpret_cast<uint32_t*>(ao + base0 + col) =
            pack_h(of[nfo][0] * inv0, of[nfo][1] * inv0);
        *reinterpret_cast<uint32_t*>(ao + base1 + col) =
            pack_h(of[nfo][2] * inv1, of[nfo][3] * inv1);
    }
}

// ---------------------------------------------------------------------------
// Host launcher
// ---------------------------------------------------------------------------
extern "C" void kernel_launch(void* const* d_in, const int* in_sizes, int n_in,
                              void* d_out, int out_size)
{
    (void)in_sizes; (void)n_in; (void)out_size;
    const float* x  = (const float*)d_in[0];
    const float* fc = (const float*)d_in[1];
    const float* wq = (const float*)d_in[2];
    const float* wk = (const float*)d_in[3];
    const float* wv = (const float*)d_in[4];
    const float* wo = (const float*)d_in[5];
    float* out = (float*)d_out;

    float* pqkv;
    __half *pxh, *pwh, *pao, *pwoh;
    __nv_bfloat16 *pqh, *pql, *pkh, *pkl, *pvth, *pvtl;
    cudaGetSymbolAddress((void**)&pqkv, g_qkv);
    cudaGetSymbolAddress((void**)&pxh,  g_xh);
    cudaGetSymbolAddress((void**)&pwh,  g_wh);
    cudaGetSymbolAddress((void**)&pao,  g_ao);
    cudaGetSymbolAddress((void**)&pwoh, g_woh);
    cudaGetSymbolAddress((void**)&pqh,  g_qh);
    cudaGetSymbolAddress((void**)&pql,  g_ql);
    cudaGetSymbolAddress((void**)&pkh,  g_kh);
    cudaGetSymbolAddress((void**)&pkl,  g_kl);
    cudaGetSymbolAddress((void**)&pvth, g_vth);
    cudaGetSymbolAddress((void**)&pvtl, g_vtl);

    cudaFuncSetAttribute(tc_gemm_f16_kernel, cudaFuncAttributeMaxDynamicSharedMemorySize,
                         GEMM_SMEM);
    cudaFuncSetAttribute(tc_gemm_qkv_kernel, cudaFuncAttributeMaxDynamicSharedMemorySize,
                         GEMM_SMEM);
    cudaFuncSetAttribute(flash_tc_kernel, cudaFuncAttributeMaxDynamicSharedMemorySize, FT_SMEM);

    // fp32 -> fp16 converts
    {
        long n4 = (long)4096 * 2048 / 4;
        cvt_h_kernel<<<(unsigned)((n4 + 255) / 256), 256>>>(x, pxh, n4);
    }
    {
        long n4 = (long)2048 * 2048 / 4;
        cvt_h_kernel<<<(unsigned)((n4 + 255) / 256), 256>>>(wq, pwh, n4);
    }
    {
        long n4 = (long)512 * 2048 / 4;
        cvt_h_kernel<<<(unsigned)((n4 + 255) / 256), 256>>>(wk, pwh + (size_t)2048 * 2048, n4);
        cvt_h_kernel<<<(unsigned)((n4 + 255) / 256), 256>>>(wv, pwh + (size_t)2560 * 2048, n4);
    }

    // QKV projection with fused RoPE epilogue
    tc_gemm_qkv_kernel<<<dim3(3072 / GBN, 4096 / GBM), 256, GEMM_SMEM>>>(
        pxh, pwh, fc, pqkv, pqh, pql, pkh, pkl);

    // V transpose -> Vt bf16 hi/lo
    vt_kernel<<<dim3(64, 4, 8), dim3(32, 8)>>>(pqkv, pvth, pvtl);

    // Tensor-core flash attention (split-bf16 + ldmatrix) -> attn out fp16
    flash_tc_kernel<<<dim3(32, 32), 128, FT_SMEM>>>(pqh, pql, pkh, pkl, pvth, pvtl, pao);

    // wo projection (fp16): [4096,2048] x [2048,2048]^T -> out
    {
        long n4 = (long)2048 * 2048 / 4;
        cvt_h_kernel<<<(unsigned)((n4 + 255) / 256), 256>>>(wo, pwoh, n4);
    }
    tc_gemm_f16_kernel<<<dim3(2048 / GBN, 4096 / GBM), 256, GEMM_SMEM>>>(
        pao, pwoh, out, 2048, 2048);
}